// round 13
// baseline (speedup 1.0000x reference)
#include <cuda_runtime.h>
#include <cuda_bf16.h>
#include <math.h>
#include <stdint.h>

#define Bn 16384
#define Dn 512
#define Kn 2048

// ======================= PTX helpers (baseline compute_103-safe) =======================
__device__ __forceinline__ uint32_t smem_to_u32(const void* p){
    uint32_t a;
    asm("{ .reg .u64 t; cvta.to.shared.u64 t, %1; cvt.u32.u64 %0, t; }" : "=r"(a) : "l"(p));
    return a;
}
#define CP_ASYNC16(dst, src) \
    asm volatile("cp.async.cg.shared.global [%0], [%1], 16;" :: "r"(dst), "l"(src) : "memory")
#define CP_COMMIT() asm volatile("cp.async.commit_group;" ::: "memory")
#define CP_WAIT(n)  asm volatile("cp.async.wait_group %0;" :: "n"(n) : "memory")
#define LDMATRIX_X4(r0,r1,r2,r3,addr) \
    asm volatile("ldmatrix.sync.aligned.m8n8.x4.shared.b16 {%0,%1,%2,%3}, [%4];" \
        : "=r"(r0),"=r"(r1),"=r"(r2),"=r"(r3) : "r"(addr))

__device__ __forceinline__ void mma16816(float* c, const uint32_t* a, const uint32_t* b){
    asm volatile("mma.sync.aligned.m16n8k16.row.col.f32.bf16.bf16.f32 "
        "{%0,%1,%2,%3}, {%4,%5,%6,%7}, {%8,%9}, {%0,%1,%2,%3};"
        : "+f"(c[0]),"+f"(c[1]),"+f"(c[2]),"+f"(c[3])
        : "r"(a[0]),"r"(a[1]),"r"(a[2]),"r"(a[3]), "r"(b[0]),"r"(b[1]));
}
__device__ __forceinline__ float2 b2f(uint32_t u){
    __nv_bfloat162 b = *reinterpret_cast<__nv_bfloat162*>(&u);
    return __bfloat1622float2(b);
}

// ======================= workspaces =======================
__device__ float g_L1[33554432];                 // [B,K] logits fp32
__device__ float g_L2[33554432];
__device__ __nv_bfloat16 g_Lb1[33554432];        // [B,K] logits bf16 (tolerant readers)
__device__ __nv_bfloat16 g_Lb2[33554432];
__device__ __nv_bfloat16 g_znh1[8388608], g_znl1[8388608];
__device__ __nv_bfloat16 g_znh2[8388608], g_znl2[8388608];
__device__ __nv_bfloat16 g_zth1[8388608], g_ztl1[8388608];
__device__ __nv_bfloat16 g_zth2[8388608], g_ztl2[8388608];
__device__ __nv_bfloat16 g_wh[1048576], g_wl[1048576];
__device__ float g_Q1[262144], g_P1[262144];
__device__ float g_Q2[262144], g_P2[262144];
__device__ float g_csum[2][512];
__device__ float g_t[2][3][2048];
__device__ float g_u1[2048], g_u2[2048], g_lu1[2048], g_lu2[2048];
__device__ float g_lse1[16384], g_lse2[16384];
__device__ int   g_am1[16384], g_am2[16384];
__device__ double g_S[2];
__device__ double g_ce[2];
__device__ float g_avgp[2048];
__device__ int   g_hist[2048];
__device__ int   g_accc[2];
__device__ float g_misc[4];

__device__ const int c_trix[10] = {0,1,1,2,2,2,3,3,3,3};
__device__ const int c_triy[10] = {0,0,1,0,1,2,0,1,2,3};

__device__ __forceinline__ float* LB(int v){ return v ? g_L2 : g_L1; }
__device__ __forceinline__ __nv_bfloat16* LBB(int v){ return v ? g_Lb2 : g_Lb1; }
__device__ __forceinline__ float* UB(int v){ return v ? g_u2 : g_u1; }
__device__ __forceinline__ float* LSEB(int v){ return v ? g_lse2 : g_lse1; }
__device__ __forceinline__ int*   AMB(int v){ return v ? g_am2 : g_am1; }

__device__ __forceinline__ void bsplit(float x, __nv_bfloat16& h, __nv_bfloat16& l){
    h = __float2bfloat16(x);
    l = __float2bfloat16(x - __bfloat162float(h));
}

// ======================= zeroing (every launch — replay idempotency) ===========
__global__ void k_zero_main(){
    int i = blockIdx.x*256 + threadIdx.x;
    g_Q1[i]=0.f; g_P1[i]=0.f; g_Q2[i]=0.f; g_P2[i]=0.f;
    if (i < 12288){ ((float*)g_t)[i]=0.f; }
    if (i < 2048){ g_avgp[i]=0.f; g_hist[i]=0; }
    if (i < 1024){ ((float*)g_csum)[i]=0.f; }
    if (i == 0){
        g_S[0]=0.0; g_S[1]=0.0; g_ce[0]=0.0; g_ce[1]=0.0;
        g_accc[0]=0; g_accc[1]=0;
        g_misc[0]=0.f; g_misc[1]=0.f; g_misc[2]=0.f; g_misc[3]=0.f;
    }
}

// ======================= row l2 normalize -> bf16 hi/lo =======================
__global__ void k_rownorm(const float* __restrict__ z, int view){
    int row = blockIdx.x, t = threadIdx.x;
    __shared__ float sm[128];
    float4 v = reinterpret_cast<const float4*>(z)[(size_t)row*128 + t];
    float s = v.x*v.x + v.y*v.y + v.z*v.z + v.w*v.w;
    sm[t]=s; __syncthreads();
    for (int o=64;o;o>>=1){ if (t<o) sm[t]+=sm[t+o]; __syncthreads(); }
    float inv = 1.f / fmaxf(sqrtf(sm[0]), 1e-12f);
    __nv_bfloat16* H = view ? g_znh2 : g_znh1;
    __nv_bfloat16* L = view ? g_znl2 : g_znl1;
    size_t o = (size_t)row*512 + t*4;
    __nv_bfloat16 h0,h1,h2,h3,l0,l1,l2,l3;
    bsplit(v.x*inv,h0,l0); bsplit(v.y*inv,h1,l1);
    bsplit(v.z*inv,h2,l2); bsplit(v.w*inv,h3,l3);
    __nv_bfloat162* Hp = reinterpret_cast<__nv_bfloat162*>(H + o);
    __nv_bfloat162* Lp = reinterpret_cast<__nv_bfloat162*>(L + o);
    Hp[0] = __nv_bfloat162(h0,h1); Hp[1] = __nv_bfloat162(h2,h3);
    Lp[0] = __nv_bfloat162(l0,l1); Lp[1] = __nv_bfloat162(l2,l3);
}

// ======================= transpose z -> zT bf16 hi/lo, + column sums ============
__global__ void k_ztrans(const float* __restrict__ z, int view){
    __shared__ float t[32][33];
    __shared__ float cs[8][32];
    __nv_bfloat16* TH = view ? g_zth2 : g_zth1;
    __nv_bfloat16* TL = view ? g_ztl2 : g_ztl1;
    int x0 = blockIdx.x*32, y0 = blockIdx.y*32;
    int tx = threadIdx.x, ty = threadIdx.y;
    #pragma unroll
    for (int i=0;i<32;i+=8)
        t[ty+i][tx] = z[(size_t)(y0+ty+i)*512 + x0 + tx];
    __syncthreads();
    cs[ty][tx] = t[ty][tx] + t[ty+8][tx] + t[ty+16][tx] + t[ty+24][tx];
    #pragma unroll
    for (int i=0;i<32;i+=8){
        float v = t[tx][ty+i];
        __nv_bfloat16 h,l; bsplit(v,h,l);
        size_t o = (size_t)(x0+ty+i)*16384 + y0 + tx;
        TH[o]=h; TL[o]=l;
    }
    __syncthreads();
    if (ty==0){
        float s = cs[0][tx]+cs[1][tx]+cs[2][tx]+cs[3][tx]
                + cs[4][tx]+cs[5][tx]+cs[6][tx]+cs[7][tx];
        atomicAdd(&g_csum[view][x0+tx], s);
    }
}

__global__ void k_wsplit(const float* __restrict__ W){
    int i = blockIdx.x*512 + threadIdx.x;
    bsplit(W[i], g_wh[i], g_wl[i]);
}

// ======= HMMA GEMM (R10 config): BM=128,BN=128,BK=32, 3-stage ring, occ 2 =======
#define SMEM_STAGE 20480
#define ROWB 80
#define G_SMEM (3*SMEM_STAGE)   // 61440

__global__ void __launch_bounds__(256,2) k_mma_gemm(int which){
    const __nv_bfloat16 *Ah,*Al,*Bh,*Bl;
    float* C; size_t ldk; int ldc, atomic_epi, KITER;
    if (which == 0){ Ah=g_znh1; Al=g_znl1; Bh=g_wh; Bl=g_wl; C=g_L1; ldk=512; ldc=2048; atomic_epi=0; KITER=48; }
    else if (which == 1){ Ah=g_znh2; Al=g_znl2; Bh=g_wh; Bl=g_wl; C=g_L2; ldk=512; ldc=2048; atomic_epi=0; KITER=48; }
    else if (which == 2){ Ah=g_zth1; Al=g_zth1; Bh=g_zth1; Bl=g_zth1; C=g_Q1; ldk=16384; ldc=512; atomic_epi=1; KITER=16; }
    else if (which == 3){ Ah=g_zth1; Al=g_zth1; Bh=g_ztl1; Bl=g_ztl1; C=g_P1; ldk=16384; ldc=512; atomic_epi=1; KITER=16; }
    else if (which == 4){ Ah=g_zth2; Al=g_zth2; Bh=g_zth2; Bl=g_zth2; C=g_Q2; ldk=16384; ldc=512; atomic_epi=1; KITER=16; }
    else { Ah=g_zth2; Al=g_zth2; Bh=g_ztl2; Bl=g_ztl2; C=g_P2; ldk=16384; ldc=512; atomic_epi=1; KITER=16; }

    extern __shared__ __align__(128) char smem[];
    uint32_t sb = smem_to_u32(smem);

    int tid = threadIdx.x;
    int wid = tid >> 5, lane = tid & 31;
    int wm = wid >> 2, wn = wid & 3;        // warp tile 64x32
    int g = lane >> 2, tig = lane & 3;

    int bxx, byy;
    if (which == 2 || which == 4){ bxx = c_trix[blockIdx.x]; byy = c_triy[blockIdx.x]; }
    else { bxx = blockIdx.x; byy = blockIdx.y; }
    int bm = byy*128, bn = bxx*128;
    size_t kz = (size_t)blockIdx.z * 512;

    const __nv_bfloat16* Aterm[3] = {Ah, Ah, Al};
    const __nv_bfloat16* Bterm[3] = {Bh, Bl, Bh};

    float acc[4][4][4];
    #pragma unroll
    for (int mf=0;mf<4;mf++)
        #pragma unroll
        for (int nf=0;nf<4;nf++)
            #pragma unroll
            for (int q=0;q<4;q++) acc[mf][nf][q]=0.f;

    int r0c = tid >> 2, c0c = tid & 3;
    int r1c = (tid+256) >> 2, c1c = tid & 3;

    auto load_stage = [&](int it, int s){
        int term = it >> 4; int kb = it & 15;
        const __nv_bfloat16* Ap = Aterm[term] + (size_t)bm*ldk + kz + kb*32;
        const __nv_bfloat16* Bp = Bterm[term] + (size_t)bn*ldk + kz + kb*32;
        uint32_t baseA = sb + s*SMEM_STAGE;
        uint32_t baseB = baseA + 10240;
        CP_ASYNC16(baseA + r0c*ROWB + c0c*16, Ap + (size_t)r0c*ldk + c0c*8);
        CP_ASYNC16(baseA + r1c*ROWB + c1c*16, Ap + (size_t)r1c*ldk + c1c*8);
        CP_ASYNC16(baseB + r0c*ROWB + c0c*16, Bp + (size_t)r0c*ldk + c0c*8);
        CP_ASYNC16(baseB + r1c*ROWB + c1c*16, Bp + (size_t)r1c*ldk + c1c*8);
        CP_COMMIT();
    };

    load_stage(0,0);
    load_stage(1,1);

    int arow_base = wm*64 + (lane&7) + ((lane>>3)&1)*8;
    int akoff     = (lane>>4)*16;
    int brow_base = wn*32 + (lane&7) + (lane>>4)*8;
    int bkoff     = ((lane>>3)&1)*16;

    int cur_s = 0, ld_s = 2;
    for (int it=0; it<KITER; it++){
        if (it+1 < KITER) { CP_WAIT(1); } else { CP_WAIT(0); }
        __syncthreads();
        if (it+2 < KITER){
            load_stage(it+2, ld_s);
            ld_s = (ld_s == 2) ? 0 : ld_s + 1;
        }
        uint32_t baseA = sb + cur_s*SMEM_STAGE;
        uint32_t baseB = baseA + 10240;
        #pragma unroll
        for (int ks=0; ks<2; ks++){
            uint32_t a[4][4], b[4][2];
            #pragma unroll
            for (int mf=0; mf<4; mf++){
                uint32_t ad = baseA + (arow_base + mf*16)*ROWB + ks*32 + akoff;
                LDMATRIX_X4(a[mf][0],a[mf][1],a[mf][2],a[mf][3], ad);
            }
            #pragma unroll
            for (int nh=0; nh<2; nh++){
                uint32_t bd = baseB + (brow_base + nh*16)*ROWB + ks*32 + bkoff;
                LDMATRIX_X4(b[nh*2][0],b[nh*2][1],b[nh*2+1][0],b[nh*2+1][1], bd);
            }
            #pragma unroll
            for (int mf=0; mf<4; mf++)
                #pragma unroll
                for (int nf=0; nf<4; nf++)
                    mma16816(acc[mf][nf], a[mf], b[nf]);
        }
        cur_s = (cur_s == 2) ? 0 : cur_s + 1;
    }

    if (!atomic_epi){
        __nv_bfloat16* Lb = LBB(which);
        #pragma unroll
        for (int mf=0; mf<4; mf++){
            int r0 = bm + wm*64 + mf*16 + g;
            #pragma unroll
            for (int nf=0; nf<4; nf++){
                int cc = bn + wn*32 + nf*8 + tig*2;
                float v00 = acc[mf][nf][0], v01 = acc[mf][nf][1];
                float v10 = acc[mf][nf][2], v11 = acc[mf][nf][3];
                *reinterpret_cast<float2*>(C + (size_t)r0*ldc + cc)     = make_float2(v00,v01);
                *reinterpret_cast<float2*>(C + (size_t)(r0+8)*ldc + cc) = make_float2(v10,v11);
                *reinterpret_cast<__nv_bfloat162*>(Lb + (size_t)r0*2048 + cc)     = __floats2bfloat162_rn(v00,v01);
                *reinterpret_cast<__nv_bfloat162*>(Lb + (size_t)(r0+8)*2048 + cc) = __floats2bfloat162_rn(v10,v11);
            }
        }
    } else {
        #pragma unroll
        for (int mf=0; mf<4; mf++){
            int r0 = bm + wm*64 + mf*16 + g;
            #pragma unroll
            for (int nf=0; nf<4; nf++){
                int cc = bn + wn*32 + nf*8 + tig*2;
                atomicAdd(C + (size_t)r0*ldc + cc,       acc[mf][nf][0]);
                atomicAdd(C + (size_t)r0*ldc + cc + 1,   acc[mf][nf][1]);
                atomicAdd(C + (size_t)(r0+8)*ldc + cc,   acc[mf][nf][2]);
                atomicAdd(C + (size_t)(r0+8)*ldc + cc+1, acc[mf][nf][3]);
            }
        }
    }
}

// ==== covariance / variance losses: G = Qsym + P + P^T ====
__global__ void k_covfin(){
    int view = blockIdx.y;
    int i = blockIdx.x, j = threadIdx.x;
    __shared__ float sm[512];
    const float* Q = view ? g_Q2 : g_Q1;
    const float* P = view ? g_P2 : g_P1;
    int bi = i >> 7, bj = j >> 7;
    float qv = (bi <= bj) ? Q[(size_t)i*512 + j] : Q[(size_t)j*512 + i];
    float raw = qv + P[(size_t)i*512 + j] + P[(size_t)j*512 + i];
    float mi = g_csum[view][i] * (1.f/16384.f);
    float mj = g_csum[view][j] * (1.f/16384.f);
    float Cij = (raw - 16384.f*mi*mj) * (1.f/16383.f);
    float c2 = (i==j) ? 0.f : Cij*Cij;
    sm[j]=c2; __syncthreads();
    for (int o=256;o;o>>=1){ if (j<o) sm[j]+=sm[j+o]; __syncthreads(); }
    if (j==0) atomicAdd(&g_misc[view*2+1], sm[0]*(1.f/512.f));
    if (j==i){
        float term = fmaxf(0.f, 0.2f - sqrtf(Cij + 1e-8f));
        atomicAdd(&g_misc[view*2+0], term*(1.f/512.f));
    }
}

// ======================= per-row max/argmax + logsumexp (fp32 L) ================
__global__ void k_rowstats(int view){
    int b = blockIdx.x, tid = threadIdx.x;
    const float* L = LB(view);
    const float4* Lr = reinterpret_cast<const float4*>(L + (size_t)b*2048);
    float4 x0 = Lr[tid*2], x1 = Lr[tid*2+1];
    float v[8] = {x0.x,x0.y,x0.z,x0.w,x1.x,x1.y,x1.z,x1.w};
    float m = v[0]; int mi = tid*8;
    #pragma unroll
    for (int j=1;j<8;j++) if (v[j]>m){ m=v[j]; mi=tid*8+j; }
    __shared__ float sm[256]; __shared__ int si[256];
    sm[tid]=m; si[tid]=mi; __syncthreads();
    for (int o=128;o;o>>=1){
        if (tid<o){
            if (sm[tid+o]>sm[tid] || (sm[tid+o]==sm[tid] && si[tid+o]<si[tid])){
                sm[tid]=sm[tid+o]; si[tid]=si[tid+o];
            }
        }
        __syncthreads();
    }
    float M = sm[0]; int gidx = si[0];
    __syncthreads();
    float se=0.f;
    #pragma unroll
    for (int j=0;j<8;j++) se += __expf((v[j]-M)*10.f);
    sm[tid]=se; __syncthreads();
    for (int o=128;o;o>>=1){ if (tid<o) sm[tid]+=sm[tid+o]; __syncthreads(); }
    if (tid==0){ LSEB(view)[b] = M*10.f + logf(sm[0]); AMB(view)[b] = gidx; }
}

// ======================= sinkhorn column pass iter0 (bf16 L) ====================
__global__ void k_colpass0(int view){
    __shared__ float sm[256];
    int k = blockIdx.x*256 + threadIdx.x;
    size_t b0 = (size_t)blockIdx.y * 128;
    const __nv_bfloat16* L = LBB(view);
    float s = 0.f;
    #pragma unroll 8
    for (int r=0;r<128;r++)
        s += __expf(20.f * __bfloat162float(L[(b0+r)*2048 + k]));
    atomicAdd(&g_t[view][0][k], s);
    sm[threadIdx.x]=s; __syncthreads();
    for (int o=128;o;o>>=1){ if (threadIdx.x<o) sm[threadIdx.x]+=sm[threadIdx.x+o]; __syncthreads(); }
    if (threadIdx.x==0) atomicAdd(&g_S[view], (double)sm[0]);
}

// ======================= u update =======================
__global__ void k_u(int iter){
    int idx = blockIdx.x*256 + threadIdx.x;
    int view = idx >> 11, k = idx & 2047;
    float t = g_t[view][iter][k];
    float u = (iter==0) ? (float)(g_S[view]) / (2048.f * t) : 1.f / (2048.f * t);
    (view ? g_u2 : g_u1)[k] = u;
    if (iter == 2) (view ? g_lu2 : g_lu1)[k] = logf(u);
}

// ========== fused sinkhorn row+col pass (bf16 L) — 1024 CTAs x 16 rows ==========
__global__ void __launch_bounds__(256) k_rowcol(int view, int iter){
    __shared__ float s_u[2048];
    __shared__ float s_v[16];
    const __nv_bfloat16* L = LBB(view);
    const float* u = UB(view);
    int tid = threadIdx.x, lane = tid & 31, wid = tid >> 5;
    for (int i=tid; i<2048; i+=256) s_u[i] = u[i];
    __syncthreads();
    int b0 = blockIdx.x * 16;
    // phase 1: warp w handles rows b0 + w*2, b0 + w*2 + 1
    #pragma unroll
    for (int rr=0; rr<2; rr++){
        int r = wid*2 + rr;
        int b = b0 + r;
        const uint4* Lr = reinterpret_cast<const uint4*>(L + (size_t)b*2048);
        float s = 0.f;
        #pragma unroll
        for (int j=0; j<8; j++){
            int c8 = j*32 + lane;
            uint4 x = Lr[c8];
            const float4* up = reinterpret_cast<const float4*>(&s_u[c8*8]);
            float4 u0 = up[0], u1 = up[1];
            float2 f0 = b2f(x.x), f1 = b2f(x.y), f2 = b2f(x.z), f3 = b2f(x.w);
            s += __expf(20.f*f0.x)*u0.x + __expf(20.f*f0.y)*u0.y
               + __expf(20.f*f1.x)*u0.z + __expf(20.f*f1.y)*u0.w
               + __expf(20.f*f2.x)*u1.x + __expf(20.f*f2.y)*u1.y
               + __expf(20.f*f3.x)*u1.z + __expf(20.f*f3.y)*u1.w;
        }
        #pragma unroll
        for (int o=16;o;o>>=1) s += __shfl_xor_sync(0xFFFFFFFFu, s, o);
        if (lane == 0) s_v[r] = 1.f / (16384.f * s);
    }
    __syncthreads();
    // phase 2: thread owns cols tid*8..+7; loop over the CTA's 16 rows
    float t8[8] = {0.f,0.f,0.f,0.f,0.f,0.f,0.f,0.f};
    const uint4* base = reinterpret_cast<const uint4*>(L) + tid;
    #pragma unroll 4
    for (int r=0; r<16; r++){
        float vv = s_v[r];
        uint4 x = base[(size_t)(b0+r)*256];
        float2 f0 = b2f(x.x), f1 = b2f(x.y), f2 = b2f(x.z), f3 = b2f(x.w);
        t8[0] += __expf(20.f*f0.x)*vv; t8[1] += __expf(20.f*f0.y)*vv;
        t8[2] += __expf(20.f*f1.x)*vv; t8[3] += __expf(20.f*f1.y)*vv;
        t8[4] += __expf(20.f*f2.x)*vv; t8[5] += __expf(20.f*f2.y)*vv;
        t8[6] += __expf(20.f*f3.x)*vv; t8[7] += __expf(20.f*f3.y)*vv;
    }
    #pragma unroll
    for (int j=0;j<8;j++) atomicAdd(&g_t[view][iter][tid*8+j], t8[j]);
}

// ===== fused final: last rowpass (v, bf16) + CE/avg_probs/acc/hist (fp32) =====
__global__ void k_final(){
    __shared__ float s_avgp[2048];
    __shared__ float s_us1[2048], s_us2[2048];
    __shared__ float s_v1[16], s_v2[16];
    __shared__ float smf[256]; __shared__ int smi[256];
    __shared__ double smd[256];
    int tid = threadIdx.x, lane = tid & 31, wid = tid >> 5;
    int kbase = tid*8;
    float U1[8],U2[8],LU1[8],LU2[8];
    #pragma unroll
    for (int j=0;j<8;j++){
        U1[j]=g_u1[kbase+j]; U2[j]=g_u2[kbase+j];
        LU1[j]=g_lu1[kbase+j]; LU2[j]=g_lu2[kbase+j];
        s_avgp[kbase+j]=0.f;
        s_us1[kbase+j]=U1[j]; s_us2[kbase+j]=U2[j];
    }
    __syncthreads();
    int b0 = blockIdx.x*16;
    #pragma unroll
    for (int rr=0; rr<2; rr++){
        int r = wid*2 + rr;
        int b = b0 + r;
        const uint4* L1r = reinterpret_cast<const uint4*>(g_Lb1 + (size_t)b*2048);
        const uint4* L2r = reinterpret_cast<const uint4*>(g_Lb2 + (size_t)b*2048);
        float s1 = 0.f, s2 = 0.f;
        #pragma unroll
        for (int j=0; j<8; j++){
            int c8 = j*32 + lane;
            uint4 x = L1r[c8];
            const float4* up = reinterpret_cast<const float4*>(&s_us1[c8*8]);
            float4 u0 = up[0], u1 = up[1];
            float2 f0 = b2f(x.x), f1 = b2f(x.y), f2 = b2f(x.z), f3 = b2f(x.w);
            s1 += __expf(20.f*f0.x)*u0.x + __expf(20.f*f0.y)*u0.y
                + __expf(20.f*f1.x)*u0.z + __expf(20.f*f1.y)*u0.w
                + __expf(20.f*f2.x)*u1.x + __expf(20.f*f2.y)*u1.y
                + __expf(20.f*f3.x)*u1.z + __expf(20.f*f3.y)*u1.w;
            uint4 y = L2r[c8];
            const float4* vp = reinterpret_cast<const float4*>(&s_us2[c8*8]);
            float4 v0 = vp[0], v1 = vp[1];
            float2 g0 = b2f(y.x), g1 = b2f(y.y), g2 = b2f(y.z), g3 = b2f(y.w);
            s2 += __expf(20.f*g0.x)*v0.x + __expf(20.f*g0.y)*v0.y
                + __expf(20.f*g1.x)*v0.z + __expf(20.f*g1.y)*v0.w
                + __expf(20.f*g2.x)*v1.x + __expf(20.f*g2.y)*v1.y
                + __expf(20.f*g3.x)*v1.z + __expf(20.f*g3.y)*v1.w;
        }
        #pragma unroll
        for (int o=16;o;o>>=1){
            s1 += __shfl_xor_sync(0xFFFFFFFFu, s1, o);
            s2 += __shfl_xor_sync(0xFFFFFFFFu, s2, o);
        }
        if (lane == 0){ s_v1[r] = s1; s_v2[r] = s2; }
    }
    __syncthreads();
    double tce1=0.0, tce2=0.0;
    int tacc1=0, tacc2=0;
    for (int r=0;r<16;r++){
        int b = b0 + r;
        const float4* L1r = reinterpret_cast<const float4*>(g_L1 + (size_t)b*2048);
        const float4* L2r = reinterpret_cast<const float4*>(g_L2 + (size_t)b*2048);
        float4 a0=L1r[tid*2], a1=L1r[tid*2+1];
        float4 c0=L2r[tid*2], c1=L2r[tid*2+1];
        float A[8]={a0.x,a0.y,a0.z,a0.w,a1.x,a1.y,a1.z,a1.w};
        float C[8]={c0.x,c0.y,c0.z,c0.w,c1.x,c1.y,c1.z,c1.w};
        float cv1 = 1.f / s_v1[r], cv2 = 1.f / s_v2[r];
        float ls1 = g_lse1[b], ls2 = g_lse2[b];
        float sc1=0.f, sc2=0.f;
        float m1=-1e30f, m2=-1e30f; int i1=0, i2=0;
        #pragma unroll
        for (int j=0;j<8;j++){
            float a=A[j], c=C[j];
            float lp1 = 10.f*a - ls1;
            float lp2 = 10.f*c - ls2;
            float t1 = cv1*U1[j]*__expf(20.f*a);
            float t2 = cv2*U2[j]*__expf(20.f*c);
            sc1 += t1*lp2;
            sc2 += t2*lp1;
            s_avgp[kbase+j] += __expf(lp1) + __expf(lp2);
            float g1 = 20.f*a + LU1[j];
            if (g1>m1){ m1=g1; i1=kbase+j; }
            float g2 = 20.f*c + LU2[j];
            if (g2>m2){ m2=g2; i2=kbase+j; }
        }
        tce1 += (double)sc1; tce2 += (double)sc2;
        smf[tid]=m2; smi[tid]=i2; __syncthreads();
        for (int o=128;o;o>>=1){
            if (tid<o && (smf[tid+o]>smf[tid] || (smf[tid+o]==smf[tid] && smi[tid+o]<smi[tid]))){
                smf[tid]=smf[tid+o]; smi[tid]=smi[tid+o];
            }
            __syncthreads();
        }
        if (tid==0 && smi[0]==g_am1[b]) tacc1++;
        __syncthreads();
        smf[tid]=m1; smi[tid]=i1; __syncthreads();
        for (int o=128;o;o>>=1){
            if (tid<o && (smf[tid+o]>smf[tid] || (smf[tid+o]==smf[tid] && smi[tid+o]<smi[tid]))){
                smf[tid]=smf[tid+o]; smi[tid]=smi[tid+o];
            }
            __syncthreads();
        }
        if (tid==0 && smi[0]==g_am2[b]) tacc2++;
        __syncthreads();
    }
    smd[tid]=tce1; __syncthreads();
    for (int o=128;o;o>>=1){ if (tid<o) smd[tid]+=smd[tid+o]; __syncthreads(); }
    if (tid==0) atomicAdd(&g_ce[0], smd[0]);
    __syncthreads();
    smd[tid]=tce2; __syncthreads();
    for (int o=128;o;o>>=1){ if (tid<o) smd[tid]+=smd[tid+o]; __syncthreads(); }
    if (tid==0) atomicAdd(&g_ce[1], smd[0]);
    __syncthreads();
    #pragma unroll
    for (int j=0;j<8;j++) atomicAdd(&g_avgp[kbase+j], s_avgp[kbase+j]);
    if (tid==0){ atomicAdd(&g_accc[0], tacc1); atomicAdd(&g_accc[1], tacc2); }
    if (tid < 16){
        atomicAdd(&g_hist[g_am1[b0+tid]], 1);
        atomicAdd(&g_hist[g_am2[b0+tid]], 1);
    }
}

__global__ void k_finalize(float* __restrict__ out){
    __shared__ double smd[256];
    int tid = threadIdx.x;
    double sh=0.0, sp=0.0;
    for (int j=0;j<8;j++){
        int k = tid*8 + j;
        double hp = (double)g_hist[k] / 32768.0;
        sh += hp * log(hp + 1e-7);
        double pp = (double)g_avgp[k] / 32768.0;
        sp += pp * log(pp + 1e-7);
    }
    smd[tid]=sh; __syncthreads();
    for (int o=128;o;o>>=1){ if (tid<o) smd[tid]+=smd[tid+o]; __syncthreads(); }
    double H = smd[0]; __syncthreads();
    smd[tid]=sp; __syncthreads();
    for (int o=128;o;o>>=1){ if (tid<o) smd[tid]+=smd[tid+o]; __syncthreads(); }
    double P = smd[0];
    if (tid==0){
        double ce = -0.5 * (g_ce[0]/16384.0 + g_ce[1]/16384.0);
        float lvar = g_misc[0] + g_misc[2];
        float lcov = g_misc[1] + g_misc[3];
        double loss = 15.0*ce + (double)lvar + (double)lcov;
        out[0] = (float)loss;
        out[1] = (float)ce;
        out[2] = lvar;
        out[3] = lcov;
        out[4] = (float)exp(-H);
        out[5] = (float)exp(-P);
        out[6] = 0.5f * ((float)g_accc[0] + (float)g_accc[1]) / 16384.f;
    }
}

// ======================= launch =======================
extern "C" void kernel_launch(void* const* d_in, const int* in_sizes, int n_in,
                              void* d_out, int out_size){
    const float* z1 = (const float*)d_in[0];
    const float* z2 = (const float*)d_in[1];
    const float* W  = (const float*)d_in[2];
    float* out = (float*)d_out;

    cudaFuncSetAttribute(k_mma_gemm, cudaFuncAttributeMaxDynamicSharedMemorySize, G_SMEM);

    // index 3 = logits GEMM (ncu -s 5 with 2 harness pre-launches)
    k_wsplit<<<2048,512>>>(W);                      // 0
    k_rownorm<<<Bn,128>>>(z1, 0);                   // 1
    k_rownorm<<<Bn,128>>>(z2, 1);                   // 2
    k_mma_gemm<<<dim3(16,128,1),256,G_SMEM>>>(0);   // 3  <- ncu target
    k_mma_gemm<<<dim3(16,128,1),256,G_SMEM>>>(1);   // 4
    k_zero_main<<<1024,256>>>();                    // 5
    k_ztrans<<<dim3(16,512),dim3(32,8)>>>(z1, 0);   // 6
    k_ztrans<<<dim3(16,512),dim3(32,8)>>>(z2, 1);   // 7
    k_mma_gemm<<<dim3(10,1,32),256,G_SMEM>>>(2);    // 8   Q1 (upper blocks)
    k_mma_gemm<<<dim3(4,4,32),256,G_SMEM>>>(3);     // 9   P1
    k_mma_gemm<<<dim3(10,1,32),256,G_SMEM>>>(4);    // 10  Q2
    k_mma_gemm<<<dim3(4,4,32),256,G_SMEM>>>(5);     // 11  P2
    k_covfin<<<dim3(512,2),512>>>();                // 12

    k_rowstats<<<Bn,256>>>(0);                      // 13
    k_rowstats<<<Bn,256>>>(1);                      // 14
    k_colpass0<<<dim3(8,128),256>>>(0);             // 15
    k_colpass0<<<dim3(8,128),256>>>(1);             // 16
    k_u<<<16,256>>>(0);                             // 17

    for (int iter=1; iter<=2; iter++){
        k_rowcol<<<1024,256>>>(0, iter);
        k_rowcol<<<1024,256>>>(1, iter);
        k_u<<<16,256>>>(iter);
    }

    k_final<<<1024,256>>>();
    k_finalize<<<1,256>>>(out);
}

// round 14
// speedup vs baseline: 1.1895x; 1.1895x over previous
#include <cuda_runtime.h>
#include <cuda_bf16.h>
#include <math.h>
#include <stdint.h>

#define Bn 16384
#define Dn 512
#define Kn 2048

// ======================= PTX helpers (baseline compute_103-safe) =======================
__device__ __forceinline__ uint32_t smem_to_u32(const void* p){
    uint32_t a;
    asm("{ .reg .u64 t; cvta.to.shared.u64 t, %1; cvt.u32.u64 %0, t; }" : "=r"(a) : "l"(p));
    return a;
}
#define CP_ASYNC16(dst, src) \
    asm volatile("cp.async.cg.shared.global [%0], [%1], 16;" :: "r"(dst), "l"(src) : "memory")
#define CP_COMMIT() asm volatile("cp.async.commit_group;" ::: "memory")
#define CP_WAIT(n)  asm volatile("cp.async.wait_group %0;" :: "n"(n) : "memory")
#define LDMATRIX_X4(r0,r1,r2,r3,addr) \
    asm volatile("ldmatrix.sync.aligned.m8n8.x4.shared.b16 {%0,%1,%2,%3}, [%4];" \
        : "=r"(r0),"=r"(r1),"=r"(r2),"=r"(r3) : "r"(addr))

__device__ __forceinline__ void mma16816(float* c, const uint32_t* a, const uint32_t* b){
    asm volatile("mma.sync.aligned.m16n8k16.row.col.f32.bf16.bf16.f32 "
        "{%0,%1,%2,%3}, {%4,%5,%6,%7}, {%8,%9}, {%0,%1,%2,%3};"
        : "+f"(c[0]),"+f"(c[1]),"+f"(c[2]),"+f"(c[3])
        : "r"(a[0]),"r"(a[1]),"r"(a[2]),"r"(a[3]), "r"(b[0]),"r"(b[1]));
}
__device__ __forceinline__ float2 b2f(uint32_t u){
    __nv_bfloat162 b = *reinterpret_cast<__nv_bfloat162*>(&u);
    return __bfloat1622float2(b);
}

// ======================= workspaces =======================
__device__ float g_L1[33554432];                 // [B,K] logits fp32
__device__ float g_L2[33554432];
__device__ __nv_bfloat16 g_Lb1[33554432];        // [B,K] logits bf16 (tolerant readers)
__device__ __nv_bfloat16 g_Lb2[33554432];
__device__ __nv_bfloat16 g_znh1[8388608], g_znl1[8388608];
__device__ __nv_bfloat16 g_znh2[8388608], g_znl2[8388608];
__device__ __nv_bfloat16 g_zth1[8388608], g_ztl1[8388608];
__device__ __nv_bfloat16 g_zth2[8388608], g_ztl2[8388608];
__device__ __nv_bfloat16 g_wh[1048576], g_wl[1048576];
__device__ float g_Q1[262144], g_P1[262144];
__device__ float g_Q2[262144], g_P2[262144];
__device__ float g_csum[2][512];
__device__ float g_t[2][3][2048];
__device__ float g_u1[2048], g_u2[2048], g_lu1[2048], g_lu2[2048];
__device__ float g_lse1[16384], g_lse2[16384];
__device__ int   g_am1[16384], g_am2[16384];
__device__ double g_S[2];
__device__ double g_ce[2];
__device__ float g_avgp[2048];
__device__ int   g_hist[2048];
__device__ int   g_accc[2];
__device__ float g_misc[4];

__device__ const int c_trix[10] = {0,1,1,2,2,2,3,3,3,3};
__device__ const int c_triy[10] = {0,0,1,0,1,2,0,1,2,3};

__device__ __forceinline__ float* LB(int v){ return v ? g_L2 : g_L1; }
__device__ __forceinline__ __nv_bfloat16* LBB(int v){ return v ? g_Lb2 : g_Lb1; }
__device__ __forceinline__ float* UB(int v){ return v ? g_u2 : g_u1; }
__device__ __forceinline__ float* LSEB(int v){ return v ? g_lse2 : g_lse1; }
__device__ __forceinline__ int*   AMB(int v){ return v ? g_am2 : g_am1; }

__device__ __forceinline__ void bsplit(float x, __nv_bfloat16& h, __nv_bfloat16& l){
    h = __float2bfloat16(x);
    l = __float2bfloat16(x - __bfloat162float(h));
}

// ======================= zeroing (every launch — replay idempotency) ===========
__global__ void k_zero_main(){
    int i = blockIdx.x*256 + threadIdx.x;
    g_Q1[i]=0.f; g_P1[i]=0.f; g_Q2[i]=0.f; g_P2[i]=0.f;
    if (i < 12288){ ((float*)g_t)[i]=0.f; }
    if (i < 2048){ g_avgp[i]=0.f; g_hist[i]=0; }
    if (i < 1024){ ((float*)g_csum)[i]=0.f; }
    if (i == 0){
        g_S[0]=0.0; g_S[1]=0.0; g_ce[0]=0.0; g_ce[1]=0.0;
        g_accc[0]=0; g_accc[1]=0;
        g_misc[0]=0.f; g_misc[1]=0.f; g_misc[2]=0.f; g_misc[3]=0.f;
    }
}

// ======================= row l2 normalize -> bf16 hi/lo =======================
__global__ void k_rownorm(const float* __restrict__ z, int view){
    int row = blockIdx.x, t = threadIdx.x;
    __shared__ float sm[128];
    float4 v = reinterpret_cast<const float4*>(z)[(size_t)row*128 + t];
    float s = v.x*v.x + v.y*v.y + v.z*v.z + v.w*v.w;
    sm[t]=s; __syncthreads();
    for (int o=64;o;o>>=1){ if (t<o) sm[t]+=sm[t+o]; __syncthreads(); }
    float inv = 1.f / fmaxf(sqrtf(sm[0]), 1e-12f);
    __nv_bfloat16* H = view ? g_znh2 : g_znh1;
    __nv_bfloat16* L = view ? g_znl2 : g_znl1;
    size_t o = (size_t)row*512 + t*4;
    __nv_bfloat16 h0,h1,h2,h3,l0,l1,l2,l3;
    bsplit(v.x*inv,h0,l0); bsplit(v.y*inv,h1,l1);
    bsplit(v.z*inv,h2,l2); bsplit(v.w*inv,h3,l3);
    __nv_bfloat162* Hp = reinterpret_cast<__nv_bfloat162*>(H + o);
    __nv_bfloat162* Lp = reinterpret_cast<__nv_bfloat162*>(L + o);
    Hp[0] = __nv_bfloat162(h0,h1); Hp[1] = __nv_bfloat162(h2,h3);
    Lp[0] = __nv_bfloat162(l0,l1); Lp[1] = __nv_bfloat162(l2,l3);
}

// ======================= transpose z -> zT bf16 hi/lo, + column sums ============
__global__ void k_ztrans(const float* __restrict__ z, int view){
    __shared__ float t[32][33];
    __shared__ float cs[8][32];
    __nv_bfloat16* TH = view ? g_zth2 : g_zth1;
    __nv_bfloat16* TL = view ? g_ztl2 : g_ztl1;
    int x0 = blockIdx.x*32, y0 = blockIdx.y*32;
    int tx = threadIdx.x, ty = threadIdx.y;
    #pragma unroll
    for (int i=0;i<32;i+=8)
        t[ty+i][tx] = z[(size_t)(y0+ty+i)*512 + x0 + tx];
    __syncthreads();
    cs[ty][tx] = t[ty][tx] + t[ty+8][tx] + t[ty+16][tx] + t[ty+24][tx];
    #pragma unroll
    for (int i=0;i<32;i+=8){
        float v = t[tx][ty+i];
        __nv_bfloat16 h,l; bsplit(v,h,l);
        size_t o = (size_t)(x0+ty+i)*16384 + y0 + tx;
        TH[o]=h; TL[o]=l;
    }
    __syncthreads();
    if (ty==0){
        float s = cs[0][tx]+cs[1][tx]+cs[2][tx]+cs[3][tx]
                + cs[4][tx]+cs[5][tx]+cs[6][tx]+cs[7][tx];
        atomicAdd(&g_csum[view][x0+tx], s);
    }
}

__global__ void k_wsplit(const float* __restrict__ W){
    int i = blockIdx.x*512 + threadIdx.x;
    bsplit(W[i], g_wh[i], g_wl[i]);
}

// ======= mega HMMA GEMM: all 6 GEMMs in one launch (flat blockIdx decode) =======
// idx [0,2048)    : logits view0   (bxx=idx&15, byy=idx>>4)
// idx [2048,4096) : logits view1
// idx +320        : Q1 (upper-tri blocks, kz 32)
// idx +512        : P1 (4x4, kz 32)
// idx +320        : Q2
// idx +512        : P2
#define SMEM_STAGE 20480
#define ROWB 80
#define G_SMEM (3*SMEM_STAGE)   // 61440

__global__ void __launch_bounds__(256,2) k_mma_all(){
    int idx = blockIdx.x;
    int which, bxx, byy, kzi;
    if (idx < 4096){
        which = idx >> 11;
        int r = idx & 2047;
        bxx = r & 15; byy = r >> 4; kzi = 0;
    } else {
        int i = idx - 4096;
        if (i < 320){ which = 2; }
        else if (i < 832){ which = 3; i -= 320; }
        else if (i < 1152){ which = 4; i -= 832; }
        else { which = 5; i -= 1152; }
        if (which == 2 || which == 4){
            int b = i % 10; bxx = c_trix[b]; byy = c_triy[b]; kzi = i / 10;
        } else {
            bxx = i & 3; byy = (i >> 2) & 3; kzi = i >> 4;
        }
    }

    const __nv_bfloat16 *Ah,*Al,*Bh,*Bl;
    float* C; size_t ldk; int ldc, atomic_epi, KITER;
    if (which == 0){ Ah=g_znh1; Al=g_znl1; Bh=g_wh; Bl=g_wl; C=g_L1; ldk=512; ldc=2048; atomic_epi=0; KITER=48; }
    else if (which == 1){ Ah=g_znh2; Al=g_znl2; Bh=g_wh; Bl=g_wl; C=g_L2; ldk=512; ldc=2048; atomic_epi=0; KITER=48; }
    else if (which == 2){ Ah=g_zth1; Al=g_zth1; Bh=g_zth1; Bl=g_zth1; C=g_Q1; ldk=16384; ldc=512; atomic_epi=1; KITER=16; }
    else if (which == 3){ Ah=g_zth1; Al=g_zth1; Bh=g_ztl1; Bl=g_ztl1; C=g_P1; ldk=16384; ldc=512; atomic_epi=1; KITER=16; }
    else if (which == 4){ Ah=g_zth2; Al=g_zth2; Bh=g_zth2; Bl=g_zth2; C=g_Q2; ldk=16384; ldc=512; atomic_epi=1; KITER=16; }
    else { Ah=g_zth2; Al=g_zth2; Bh=g_ztl2; Bl=g_ztl2; C=g_P2; ldk=16384; ldc=512; atomic_epi=1; KITER=16; }

    extern __shared__ __align__(128) char smem[];
    uint32_t sb = smem_to_u32(smem);

    int tid = threadIdx.x;
    int wid = tid >> 5, lane = tid & 31;
    int wm = wid >> 2, wn = wid & 3;        // warp tile 64x32
    int g = lane >> 2, tig = lane & 3;

    int bm = byy*128, bn = bxx*128;
    size_t kz = (size_t)kzi * 512;

    const __nv_bfloat16* Aterm[3] = {Ah, Ah, Al};
    const __nv_bfloat16* Bterm[3] = {Bh, Bl, Bh};

    float acc[4][4][4];
    #pragma unroll
    for (int mf=0;mf<4;mf++)
        #pragma unroll
        for (int nf=0;nf<4;nf++)
            #pragma unroll
            for (int q=0;q<4;q++) acc[mf][nf][q]=0.f;

    int r0c = tid >> 2, c0c = tid & 3;
    int r1c = (tid+256) >> 2, c1c = tid & 3;

    auto load_stage = [&](int it, int s){
        int term = it >> 4; int kb = it & 15;
        const __nv_bfloat16* Ap = Aterm[term] + (size_t)bm*ldk + kz + kb*32;
        const __nv_bfloat16* Bp = Bterm[term] + (size_t)bn*ldk + kz + kb*32;
        uint32_t baseA = sb + s*SMEM_STAGE;
        uint32_t baseB = baseA + 10240;
        CP_ASYNC16(baseA + r0c*ROWB + c0c*16, Ap + (size_t)r0c*ldk + c0c*8);
        CP_ASYNC16(baseA + r1c*ROWB + c1c*16, Ap + (size_t)r1c*ldk + c1c*8);
        CP_ASYNC16(baseB + r0c*ROWB + c0c*16, Bp + (size_t)r0c*ldk + c0c*8);
        CP_ASYNC16(baseB + r1c*ROWB + c1c*16, Bp + (size_t)r1c*ldk + c1c*8);
        CP_COMMIT();
    };

    load_stage(0,0);
    load_stage(1,1);

    int arow_base = wm*64 + (lane&7) + ((lane>>3)&1)*8;
    int akoff     = (lane>>4)*16;
    int brow_base = wn*32 + (lane&7) + (lane>>4)*8;
    int bkoff     = ((lane>>3)&1)*16;

    int cur_s = 0, ld_s = 2;
    for (int it=0; it<KITER; it++){
        if (it+1 < KITER) { CP_WAIT(1); } else { CP_WAIT(0); }
        __syncthreads();
        if (it+2 < KITER){
            load_stage(it+2, ld_s);
            ld_s = (ld_s == 2) ? 0 : ld_s + 1;
        }
        uint32_t baseA = sb + cur_s*SMEM_STAGE;
        uint32_t baseB = baseA + 10240;
        #pragma unroll
        for (int ks=0; ks<2; ks++){
            uint32_t a[4][4], b[4][2];
            #pragma unroll
            for (int mf=0; mf<4; mf++){
                uint32_t ad = baseA + (arow_base + mf*16)*ROWB + ks*32 + akoff;
                LDMATRIX_X4(a[mf][0],a[mf][1],a[mf][2],a[mf][3], ad);
            }
            #pragma unroll
            for (int nh=0; nh<2; nh++){
                uint32_t bd = baseB + (brow_base + nh*16)*ROWB + ks*32 + bkoff;
                LDMATRIX_X4(b[nh*2][0],b[nh*2][1],b[nh*2+1][0],b[nh*2+1][1], bd);
            }
            #pragma unroll
            for (int mf=0; mf<4; mf++)
                #pragma unroll
                for (int nf=0; nf<4; nf++)
                    mma16816(acc[mf][nf], a[mf], b[nf]);
        }
        cur_s = (cur_s == 2) ? 0 : cur_s + 1;
    }

    if (!atomic_epi){
        __nv_bfloat16* Lb = LBB(which);
        #pragma unroll
        for (int mf=0; mf<4; mf++){
            int r0 = bm + wm*64 + mf*16 + g;
            #pragma unroll
            for (int nf=0; nf<4; nf++){
                int cc = bn + wn*32 + nf*8 + tig*2;
                float v00 = acc[mf][nf][0], v01 = acc[mf][nf][1];
                float v10 = acc[mf][nf][2], v11 = acc[mf][nf][3];
                *reinterpret_cast<float2*>(C + (size_t)r0*ldc + cc)     = make_float2(v00,v01);
                *reinterpret_cast<float2*>(C + (size_t)(r0+8)*ldc + cc) = make_float2(v10,v11);
                *reinterpret_cast<__nv_bfloat162*>(Lb + (size_t)r0*2048 + cc)     = __floats2bfloat162_rn(v00,v01);
                *reinterpret_cast<__nv_bfloat162*>(Lb + (size_t)(r0+8)*2048 + cc) = __floats2bfloat162_rn(v10,v11);
            }
        }
    } else {
        #pragma unroll
        for (int mf=0; mf<4; mf++){
            int r0 = bm + wm*64 + mf*16 + g;
            #pragma unroll
            for (int nf=0; nf<4; nf++){
                int cc = bn + wn*32 + nf*8 + tig*2;
                atomicAdd(C + (size_t)r0*ldc + cc,       acc[mf][nf][0]);
                atomicAdd(C + (size_t)r0*ldc + cc + 1,   acc[mf][nf][1]);
                atomicAdd(C + (size_t)(r0+8)*ldc + cc,   acc[mf][nf][2]);
                atomicAdd(C + (size_t)(r0+8)*ldc + cc+1, acc[mf][nf][3]);
            }
        }
    }
}

// ==== covariance / variance losses: G = Qsym + P + P^T ====
__global__ void k_covfin(){
    int view = blockIdx.y;
    int i = blockIdx.x, j = threadIdx.x;
    __shared__ float sm[512];
    const float* Q = view ? g_Q2 : g_Q1;
    const float* P = view ? g_P2 : g_P1;
    int bi = i >> 7, bj = j >> 7;
    float qv = (bi <= bj) ? Q[(size_t)i*512 + j] : Q[(size_t)j*512 + i];
    float raw = qv + P[(size_t)i*512 + j] + P[(size_t)j*512 + i];
    float mi = g_csum[view][i] * (1.f/16384.f);
    float mj = g_csum[view][j] * (1.f/16384.f);
    float Cij = (raw - 16384.f*mi*mj) * (1.f/16383.f);
    float c2 = (i==j) ? 0.f : Cij*Cij;
    sm[j]=c2; __syncthreads();
    for (int o=256;o;o>>=1){ if (j<o) sm[j]+=sm[j+o]; __syncthreads(); }
    if (j==0) atomicAdd(&g_misc[view*2+1], sm[0]*(1.f/512.f));
    if (j==i){
        float term = fmaxf(0.f, 0.2f - sqrtf(Cij + 1e-8f));
        atomicAdd(&g_misc[view*2+0], term*(1.f/512.f));
    }
}

// ======================= per-row max/argmax + logsumexp (fp32 L, both views) ====
__global__ void k_rowstats(){
    int view = blockIdx.y;
    int b = blockIdx.x, tid = threadIdx.x;
    const float* L = LB(view);
    const float4* Lr = reinterpret_cast<const float4*>(L + (size_t)b*2048);
    float4 x0 = Lr[tid*2], x1 = Lr[tid*2+1];
    float v[8] = {x0.x,x0.y,x0.z,x0.w,x1.x,x1.y,x1.z,x1.w};
    float m = v[0]; int mi = tid*8;
    #pragma unroll
    for (int j=1;j<8;j++) if (v[j]>m){ m=v[j]; mi=tid*8+j; }
    __shared__ float sm[256]; __shared__ int si[256];
    sm[tid]=m; si[tid]=mi; __syncthreads();
    for (int o=128;o;o>>=1){
        if (tid<o){
            if (sm[tid+o]>sm[tid] || (sm[tid+o]==sm[tid] && si[tid+o]<si[tid])){
                sm[tid]=sm[tid+o]; si[tid]=si[tid+o];
            }
        }
        __syncthreads();
    }
    float M = sm[0]; int gidx = si[0];
    __syncthreads();
    float se=0.f;
    #pragma unroll
    for (int j=0;j<8;j++) se += __expf((v[j]-M)*10.f);
    sm[tid]=se; __syncthreads();
    for (int o=128;o;o>>=1){ if (tid<o) sm[tid]+=sm[tid+o]; __syncthreads(); }
    if (tid==0){ LSEB(view)[b] = M*10.f + logf(sm[0]); AMB(view)[b] = gidx; }
}

// ======================= sinkhorn column pass iter0 (bf16 L, both views) ========
__global__ void k_colpass0(){
    int view = blockIdx.z;
    __shared__ float sm[256];
    int k = blockIdx.x*256 + threadIdx.x;
    size_t b0 = (size_t)blockIdx.y * 128;
    const __nv_bfloat16* L = LBB(view);
    float s = 0.f;
    #pragma unroll 8
    for (int r=0;r<128;r++)
        s += __expf(20.f * __bfloat162float(L[(b0+r)*2048 + k]));
    atomicAdd(&g_t[view][0][k], s);
    sm[threadIdx.x]=s; __syncthreads();
    for (int o=128;o;o>>=1){ if (threadIdx.x<o) sm[threadIdx.x]+=sm[threadIdx.x+o]; __syncthreads(); }
    if (threadIdx.x==0) atomicAdd(&g_S[view], (double)sm[0]);
}

// ======================= u update =======================
__global__ void k_u(int iter){
    int idx = blockIdx.x*256 + threadIdx.x;
    int view = idx >> 11, k = idx & 2047;
    float t = g_t[view][iter][k];
    float u = (iter==0) ? (float)(g_S[view]) / (2048.f * t) : 1.f / (2048.f * t);
    (view ? g_u2 : g_u1)[k] = u;
    if (iter == 2) (view ? g_lu2 : g_lu1)[k] = logf(u);
}

// ========== fused sinkhorn row+col pass (bf16 L) — grid (256, 2 views) ==========
__global__ void __launch_bounds__(256) k_rowcol(int iter){
    int view = blockIdx.y;
    __shared__ float s_u[2048];
    __shared__ float s_v[64];
    const __nv_bfloat16* L = LBB(view);
    const float* u = UB(view);
    int tid = threadIdx.x, lane = tid & 31, wid = tid >> 5;
    for (int i=tid; i<2048; i+=256) s_u[i] = u[i];
    __syncthreads();
    int b0 = blockIdx.x * 64;
    for (int r=0; r<8; r++){
        int b = b0 + wid*8 + r;
        const uint4* Lr = reinterpret_cast<const uint4*>(L + (size_t)b*2048);
        float s = 0.f;
        #pragma unroll
        for (int j=0; j<8; j++){
            int c8 = j*32 + lane;
            uint4 x = Lr[c8];
            const float4* up = reinterpret_cast<const float4*>(&s_u[c8*8]);
            float4 u0 = up[0], u1 = up[1];
            float2 f0 = b2f(x.x), f1 = b2f(x.y), f2 = b2f(x.z), f3 = b2f(x.w);
            s += __expf(20.f*f0.x)*u0.x + __expf(20.f*f0.y)*u0.y
               + __expf(20.f*f1.x)*u0.z + __expf(20.f*f1.y)*u0.w
               + __expf(20.f*f2.x)*u1.x + __expf(20.f*f2.y)*u1.y
               + __expf(20.f*f3.x)*u1.z + __expf(20.f*f3.y)*u1.w;
        }
        #pragma unroll
        for (int o=16;o;o>>=1) s += __shfl_xor_sync(0xFFFFFFFFu, s, o);
        if (lane == 0) s_v[wid*8+r] = 1.f / (16384.f * s);
    }
    __syncthreads();
    float t8[8] = {0.f,0.f,0.f,0.f,0.f,0.f,0.f,0.f};
    const uint4* base = reinterpret_cast<const uint4*>(L) + tid;
    for (int r=0; r<64; r++){
        float vv = s_v[r];
        uint4 x = base[(size_t)(b0+r)*256];
        float2 f0 = b2f(x.x), f1 = b2f(x.y), f2 = b2f(x.z), f3 = b2f(x.w);
        t8[0] += __expf(20.f*f0.x)*vv; t8[1] += __expf(20.f*f0.y)*vv;
        t8[2] += __expf(20.f*f1.x)*vv; t8[3] += __expf(20.f*f1.y)*vv;
        t8[4] += __expf(20.f*f2.x)*vv; t8[5] += __expf(20.f*f2.y)*vv;
        t8[6] += __expf(20.f*f3.x)*vv; t8[7] += __expf(20.f*f3.y)*vv;
    }
    #pragma unroll
    for (int j=0;j<8;j++) atomicAdd(&g_t[view][iter][tid*8+j], t8[j]);
}

// ===== fused final: last rowpass (v, bf16) + CE/avg_probs/acc/hist (fp32) =====
__global__ void k_final(){
    __shared__ float s_avgp[2048];
    __shared__ float s_us1[2048], s_us2[2048];
    __shared__ float s_v1[16], s_v2[16];
    __shared__ float smf[256]; __shared__ int smi[256];
    __shared__ double smd[256];
    int tid = threadIdx.x, lane = tid & 31, wid = tid >> 5;
    int kbase = tid*8;
    float U1[8],U2[8],LU1[8],LU2[8];
    #pragma unroll
    for (int j=0;j<8;j++){
        U1[j]=g_u1[kbase+j]; U2[j]=g_u2[kbase+j];
        LU1[j]=g_lu1[kbase+j]; LU2[j]=g_lu2[kbase+j];
        s_avgp[kbase+j]=0.f;
        s_us1[kbase+j]=U1[j]; s_us2[kbase+j]=U2[j];
    }
    __syncthreads();
    int b0 = blockIdx.x*16;
    #pragma unroll
    for (int rr=0; rr<2; rr++){
        int r = wid*2 + rr;
        int b = b0 + r;
        const uint4* L1r = reinterpret_cast<const uint4*>(g_Lb1 + (size_t)b*2048);
        const uint4* L2r = reinterpret_cast<const uint4*>(g_Lb2 + (size_t)b*2048);
        float s1 = 0.f, s2 = 0.f;
        #pragma unroll
        for (int j=0; j<8; j++){
            int c8 = j*32 + lane;
            uint4 x = L1r[c8];
            const float4* up = reinterpret_cast<const float4*>(&s_us1[c8*8]);
            float4 u0 = up[0], u1 = up[1];
            float2 f0 = b2f(x.x), f1 = b2f(x.y), f2 = b2f(x.z), f3 = b2f(x.w);
            s1 += __expf(20.f*f0.x)*u0.x + __expf(20.f*f0.y)*u0.y
                + __expf(20.f*f1.x)*u0.z + __expf(20.f*f1.y)*u0.w
                + __expf(20.f*f2.x)*u1.x + __expf(20.f*f2.y)*u1.y
                + __expf(20.f*f3.x)*u1.z + __expf(20.f*f3.y)*u1.w;
            uint4 y = L2r[c8];
            const float4* vp = reinterpret_cast<const float4*>(&s_us2[c8*8]);
            float4 v0 = vp[0], v1 = vp[1];
            float2 g0 = b2f(y.x), g1 = b2f(y.y), g2 = b2f(y.z), g3 = b2f(y.w);
            s2 += __expf(20.f*g0.x)*v0.x + __expf(20.f*g0.y)*v0.y
                + __expf(20.f*g1.x)*v0.z + __expf(20.f*g1.y)*v0.w
                + __expf(20.f*g2.x)*v1.x + __expf(20.f*g2.y)*v1.y
                + __expf(20.f*g3.x)*v1.z + __expf(20.f*g3.y)*v1.w;
        }
        #pragma unroll
        for (int o=16;o;o>>=1){
            s1 += __shfl_xor_sync(0xFFFFFFFFu, s1, o);
            s2 += __shfl_xor_sync(0xFFFFFFFFu, s2, o);
        }
        if (lane == 0){ s_v1[r] = s1; s_v2[r] = s2; }
    }
    __syncthreads();
    double tce1=0.0, tce2=0.0;
    int tacc1=0, tacc2=0;
    for (int r=0;r<16;r++){
        int b = b0 + r;
        const float4* L1r = reinterpret_cast<const float4*>(g_L1 + (size_t)b*2048);
        const float4* L2r = reinterpret_cast<const float4*>(g_L2 + (size_t)b*2048);
        float4 a0=L1r[tid*2], a1=L1r[tid*2+1];
        float4 c0=L2r[tid*2], c1=L2r[tid*2+1];
        float A[8]={a0.x,a0.y,a0.z,a0.w,a1.x,a1.y,a1.z,a1.w};
        float C[8]={c0.x,c0.y,c0.z,c0.w,c1.x,c1.y,c1.z,c1.w};
        float cv1 = 1.f / s_v1[r], cv2 = 1.f / s_v2[r];
        float ls1 = g_lse1[b], ls2 = g_lse2[b];
        float sc1=0.f, sc2=0.f;
        float m1=-1e30f, m2=-1e30f; int i1=0, i2=0;
        #pragma unroll
        for (int j=0;j<8;j++){
            float a=A[j], c=C[j];
            float lp1 = 10.f*a - ls1;
            float lp2 = 10.f*c - ls2;
            float t1 = cv1*U1[j]*__expf(20.f*a);
            float t2 = cv2*U2[j]*__expf(20.f*c);
            sc1 += t1*lp2;
            sc2 += t2*lp1;
            s_avgp[kbase+j] += __expf(lp1) + __expf(lp2);
            float g1 = 20.f*a + LU1[j];
            if (g1>m1){ m1=g1; i1=kbase+j; }
            float g2 = 20.f*c + LU2[j];
            if (g2>m2){ m2=g2; i2=kbase+j; }
        }
        tce1 += (double)sc1; tce2 += (double)sc2;
        smf[tid]=m2; smi[tid]=i2; __syncthreads();
        for (int o=128;o;o>>=1){
            if (tid<o && (smf[tid+o]>smf[tid] || (smf[tid+o]==smf[tid] && smi[tid+o]<smi[tid]))){
                smf[tid]=smf[tid+o]; smi[tid]=smi[tid+o];
            }
            __syncthreads();
        }
        if (tid==0 && smi[0]==g_am1[b]) tacc1++;
        __syncthreads();
        smf[tid]=m1; smi[tid]=i1; __syncthreads();
        for (int o=128;o;o>>=1){
            if (tid<o && (smf[tid+o]>smf[tid] || (smf[tid+o]==smf[tid] && smi[tid+o]<smi[tid]))){
                smf[tid]=smf[tid+o]; smi[tid]=smi[tid+o];
            }
            __syncthreads();
        }
        if (tid==0 && smi[0]==g_am2[b]) tacc2++;
        __syncthreads();
    }
    smd[tid]=tce1; __syncthreads();
    for (int o=128;o;o>>=1){ if (tid<o) smd[tid]+=smd[tid+o]; __syncthreads(); }
    if (tid==0) atomicAdd(&g_ce[0], smd[0]);
    __syncthreads();
    smd[tid]=tce2; __syncthreads();
    for (int o=128;o;o>>=1){ if (tid<o) smd[tid]+=smd[tid+o]; __syncthreads(); }
    if (tid==0) atomicAdd(&g_ce[1], smd[0]);
    __syncthreads();
    #pragma unroll
    for (int j=0;j<8;j++) atomicAdd(&g_avgp[kbase+j], s_avgp[kbase+j]);
    if (tid==0){ atomicAdd(&g_accc[0], tacc1); atomicAdd(&g_accc[1], tacc2); }
    if (tid < 16){
        atomicAdd(&g_hist[g_am1[b0+tid]], 1);
        atomicAdd(&g_hist[g_am2[b0+tid]], 1);
    }
}

__global__ void k_finalize(float* __restrict__ out){
    __shared__ double smd[256];
    int tid = threadIdx.x;
    double sh=0.0, sp=0.0;
    for (int j=0;j<8;j++){
        int k = tid*8 + j;
        double hp = (double)g_hist[k] / 32768.0;
        sh += hp * log(hp + 1e-7);
        double pp = (double)g_avgp[k] / 32768.0;
        sp += pp * log(pp + 1e-7);
    }
    smd[tid]=sh; __syncthreads();
    for (int o=128;o;o>>=1){ if (tid<o) smd[tid]+=smd[tid+o]; __syncthreads(); }
    double H = smd[0]; __syncthreads();
    smd[tid]=sp; __syncthreads();
    for (int o=128;o;o>>=1){ if (tid<o) smd[tid]+=smd[tid+o]; __syncthreads(); }
    double P = smd[0];
    if (tid==0){
        double ce = -0.5 * (g_ce[0]/16384.0 + g_ce[1]/16384.0);
        float lvar = g_misc[0] + g_misc[2];
        float lcov = g_misc[1] + g_misc[3];
        double loss = 15.0*ce + (double)lvar + (double)lcov;
        out[0] = (float)loss;
        out[1] = (float)ce;
        out[2] = lvar;
        out[3] = lcov;
        out[4] = (float)exp(-H);
        out[5] = (float)exp(-P);
        out[6] = 0.5f * ((float)g_accc[0] + (float)g_accc[1]) / 16384.f;
    }
}

// ======================= launch =======================
extern "C" void kernel_launch(void* const* d_in, const int* in_sizes, int n_in,
                              void* d_out, int out_size){
    const float* z1 = (const float*)d_in[0];
    const float* z2 = (const float*)d_in[1];
    const float* W  = (const float*)d_in[2];
    float* out = (float*)d_out;

    cudaFuncSetAttribute(k_mma_all, cudaFuncAttributeMaxDynamicSharedMemorySize, G_SMEM);

    k_wsplit<<<2048,512>>>(W);                      // 0
    k_zero_main<<<1024,256>>>();                    // 1
    k_rownorm<<<Bn,128>>>(z1, 0);                   // 2
    k_rownorm<<<Bn,128>>>(z2, 1);                   // 3
    k_ztrans<<<dim3(16,512),dim3(32,8)>>>(z1, 0);   // 4
    k_ztrans<<<dim3(16,512),dim3(32,8)>>>(z2, 1);   // 5
    k_mma_all<<<5760,256,G_SMEM>>>();               // 6  all 6 GEMMs
    k_covfin<<<dim3(512,2),512>>>();                // 7
    k_rowstats<<<dim3(Bn,2),256>>>();               // 8
    k_colpass0<<<dim3(8,128,2),256>>>();            // 9
    k_u<<<16,256>>>(0);                             // 10

    for (int iter=1; iter<=2; iter++){
        k_rowcol<<<dim3(256,2),256>>>(iter);
        k_u<<<16,256>>>(iter);
    }

    k_final<<<1024,256>>>();
    k_finalize<<<1,256>>>(out);
}

// round 15
// speedup vs baseline: 1.1961x; 1.0056x over previous
#include <cuda_runtime.h>
#include <cuda_bf16.h>
#include <math.h>
#include <stdint.h>

#define Bn 16384
#define Dn 512
#define Kn 2048

// ======================= PTX helpers (baseline compute_103-safe) =======================
__device__ __forceinline__ uint32_t smem_to_u32(const void* p){
    uint32_t a;
    asm("{ .reg .u64 t; cvta.to.shared.u64 t, %1; cvt.u32.u64 %0, t; }" : "=r"(a) : "l"(p));
    return a;
}
#define CP_ASYNC16(dst, src) \
    asm volatile("cp.async.cg.shared.global [%0], [%1], 16;" :: "r"(dst), "l"(src) : "memory")
#define CP_COMMIT() asm volatile("cp.async.commit_group;" ::: "memory")
#define CP_WAIT(n)  asm volatile("cp.async.wait_group %0;" :: "n"(n) : "memory")
#define LDMATRIX_X4(r0,r1,r2,r3,addr) \
    asm volatile("ldmatrix.sync.aligned.m8n8.x4.shared.b16 {%0,%1,%2,%3}, [%4];" \
        : "=r"(r0),"=r"(r1),"=r"(r2),"=r"(r3) : "r"(addr))

__device__ __forceinline__ void mma16816(float* c, const uint32_t* a, const uint32_t* b){
    asm volatile("mma.sync.aligned.m16n8k16.row.col.f32.bf16.bf16.f32 "
        "{%0,%1,%2,%3}, {%4,%5,%6,%7}, {%8,%9}, {%0,%1,%2,%3};"
        : "+f"(c[0]),"+f"(c[1]),"+f"(c[2]),"+f"(c[3])
        : "r"(a[0]),"r"(a[1]),"r"(a[2]),"r"(a[3]), "r"(b[0]),"r"(b[1]));
}
__device__ __forceinline__ float2 b2f(uint32_t u){
    __nv_bfloat162 b = *reinterpret_cast<__nv_bfloat162*>(&u);
    return __bfloat1622float2(b);
}

// ======================= workspaces =======================
__device__ float g_L1[33554432];                 // [B,K] logits fp32
__device__ float g_L2[33554432];
__device__ __nv_bfloat16 g_Lb1[33554432];        // [B,K] logits bf16 (tolerant readers)
__device__ __nv_bfloat16 g_Lb2[33554432];
__device__ __nv_bfloat16 g_znh1[8388608], g_znl1[8388608];
__device__ __nv_bfloat16 g_znh2[8388608], g_znl2[8388608];
__device__ __nv_bfloat16 g_zth1[8388608], g_ztl1[8388608];
__device__ __nv_bfloat16 g_zth2[8388608], g_ztl2[8388608];
__device__ __nv_bfloat16 g_wh[1048576], g_wl[1048576];
__device__ float g_Q1[262144], g_P1[262144];
__device__ float g_Q2[262144], g_P2[262144];
__device__ float g_csum[2][512];
__device__ float g_t[2][3][2048];
__device__ double g_S[2];
__device__ double g_ce[2];
__device__ float g_avgp[2048];
__device__ int   g_hist[2048];
__device__ int   g_accc[2];
__device__ float g_misc[4];

__device__ const int c_trix[10] = {0,1,1,2,2,2,3,3,3,3};
__device__ const int c_triy[10] = {0,0,1,0,1,2,0,1,2,3};

__device__ __forceinline__ float* LB(int v){ return v ? g_L2 : g_L1; }
__device__ __forceinline__ __nv_bfloat16* LBB(int v){ return v ? g_Lb2 : g_Lb1; }

__device__ __forceinline__ void bsplit(float x, __nv_bfloat16& h, __nv_bfloat16& l){
    h = __float2bfloat16(x);
    l = __float2bfloat16(x - __bfloat162float(h));
}

// ======================= zeroing (every launch — replay idempotency) ===========
__global__ void k_zero_main(){
    int i = blockIdx.x*256 + threadIdx.x;
    g_Q1[i]=0.f; g_P1[i]=0.f; g_Q2[i]=0.f; g_P2[i]=0.f;
    if (i < 12288){ ((float*)g_t)[i]=0.f; }
    if (i < 2048){ g_avgp[i]=0.f; g_hist[i]=0; }
    if (i < 1024){ ((float*)g_csum)[i]=0.f; }
    if (i == 0){
        g_S[0]=0.0; g_S[1]=0.0; g_ce[0]=0.0; g_ce[1]=0.0;
        g_accc[0]=0; g_accc[1]=0;
        g_misc[0]=0.f; g_misc[1]=0.f; g_misc[2]=0.f; g_misc[3]=0.f;
    }
}

// ======================= row l2 normalize -> bf16 hi/lo =======================
__global__ void k_rownorm(const float* __restrict__ z, int view){
    int row = blockIdx.x, t = threadIdx.x;
    __shared__ float sm[128];
    float4 v = reinterpret_cast<const float4*>(z)[(size_t)row*128 + t];
    float s = v.x*v.x + v.y*v.y + v.z*v.z + v.w*v.w;
    sm[t]=s; __syncthreads();
    for (int o=64;o;o>>=1){ if (t<o) sm[t]+=sm[t+o]; __syncthreads(); }
    float inv = 1.f / fmaxf(sqrtf(sm[0]), 1e-12f);
    __nv_bfloat16* H = view ? g_znh2 : g_znh1;
    __nv_bfloat16* L = view ? g_znl2 : g_znl1;
    size_t o = (size_t)row*512 + t*4;
    __nv_bfloat16 h0,h1,h2,h3,l0,l1,l2,l3;
    bsplit(v.x*inv,h0,l0); bsplit(v.y*inv,h1,l1);
    bsplit(v.z*inv,h2,l2); bsplit(v.w*inv,h3,l3);
    __nv_bfloat162* Hp = reinterpret_cast<__nv_bfloat162*>(H + o);
    __nv_bfloat162* Lp = reinterpret_cast<__nv_bfloat162*>(L + o);
    Hp[0] = __nv_bfloat162(h0,h1); Hp[1] = __nv_bfloat162(h2,h3);
    Lp[0] = __nv_bfloat162(l0,l1); Lp[1] = __nv_bfloat162(l2,l3);
}

// ======================= transpose z -> zT bf16 hi/lo, + column sums ============
__global__ void k_ztrans(const float* __restrict__ z, int view){
    __shared__ float t[32][33];
    __shared__ float cs[8][32];
    __nv_bfloat16* TH = view ? g_zth2 : g_zth1;
    __nv_bfloat16* TL = view ? g_ztl2 : g_ztl1;
    int x0 = blockIdx.x*32, y0 = blockIdx.y*32;
    int tx = threadIdx.x, ty = threadIdx.y;
    #pragma unroll
    for (int i=0;i<32;i+=8)
        t[ty+i][tx] = z[(size_t)(y0+ty+i)*512 + x0 + tx];
    __syncthreads();
    cs[ty][tx] = t[ty][tx] + t[ty+8][tx] + t[ty+16][tx] + t[ty+24][tx];
    #pragma unroll
    for (int i=0;i<32;i+=8){
        float v = t[tx][ty+i];
        __nv_bfloat16 h,l; bsplit(v,h,l);
        size_t o = (size_t)(x0+ty+i)*16384 + y0 + tx;
        TH[o]=h; TL[o]=l;
    }
    __syncthreads();
    if (ty==0){
        float s = cs[0][tx]+cs[1][tx]+cs[2][tx]+cs[3][tx]
                + cs[4][tx]+cs[5][tx]+cs[6][tx]+cs[7][tx];
        atomicAdd(&g_csum[view][x0+tx], s);
    }
}

__global__ void k_wsplit(const float* __restrict__ W){
    int i = blockIdx.x*512 + threadIdx.x;
    bsplit(W[i], g_wh[i], g_wl[i]);
}

// ======= mega HMMA GEMM: all 6 GEMMs in one launch (flat blockIdx decode) =======
#define SMEM_STAGE 20480
#define ROWB 80
#define G_SMEM (3*SMEM_STAGE)   // 61440

__global__ void __launch_bounds__(256,2) k_mma_all(){
    int idx = blockIdx.x;
    int which, bxx, byy, kzi;
    if (idx < 4096){
        which = idx >> 11;
        int r = idx & 2047;
        bxx = r & 15; byy = r >> 4; kzi = 0;
    } else {
        int i = idx - 4096;
        if (i < 320){ which = 2; }
        else if (i < 832){ which = 3; i -= 320; }
        else if (i < 1152){ which = 4; i -= 832; }
        else { which = 5; i -= 1152; }
        if (which == 2 || which == 4){
            int b = i % 10; bxx = c_trix[b]; byy = c_triy[b]; kzi = i / 10;
        } else {
            bxx = i & 3; byy = (i >> 2) & 3; kzi = i >> 4;
        }
    }

    const __nv_bfloat16 *Ah,*Al,*Bh,*Bl;
    float* C; size_t ldk; int ldc, atomic_epi, KITER;
    if (which == 0){ Ah=g_znh1; Al=g_znl1; Bh=g_wh; Bl=g_wl; C=g_L1; ldk=512; ldc=2048; atomic_epi=0; KITER=48; }
    else if (which == 1){ Ah=g_znh2; Al=g_znl2; Bh=g_wh; Bl=g_wl; C=g_L2; ldk=512; ldc=2048; atomic_epi=0; KITER=48; }
    else if (which == 2){ Ah=g_zth1; Al=g_zth1; Bh=g_zth1; Bl=g_zth1; C=g_Q1; ldk=16384; ldc=512; atomic_epi=1; KITER=16; }
    else if (which == 3){ Ah=g_zth1; Al=g_zth1; Bh=g_ztl1; Bl=g_ztl1; C=g_P1; ldk=16384; ldc=512; atomic_epi=1; KITER=16; }
    else if (which == 4){ Ah=g_zth2; Al=g_zth2; Bh=g_zth2; Bl=g_zth2; C=g_Q2; ldk=16384; ldc=512; atomic_epi=1; KITER=16; }
    else { Ah=g_zth2; Al=g_zth2; Bh=g_ztl2; Bl=g_ztl2; C=g_P2; ldk=16384; ldc=512; atomic_epi=1; KITER=16; }

    extern __shared__ __align__(128) char smem[];
    uint32_t sb = smem_to_u32(smem);

    int tid = threadIdx.x;
    int wid = tid >> 5, lane = tid & 31;
    int wm = wid >> 2, wn = wid & 3;
    int g = lane >> 2, tig = lane & 3;

    int bm = byy*128, bn = bxx*128;
    size_t kz = (size_t)kzi * 512;

    const __nv_bfloat16* Aterm[3] = {Ah, Ah, Al};
    const __nv_bfloat16* Bterm[3] = {Bh, Bl, Bh};

    float acc[4][4][4];
    #pragma unroll
    for (int mf=0;mf<4;mf++)
        #pragma unroll
        for (int nf=0;nf<4;nf++)
            #pragma unroll
            for (int q=0;q<4;q++) acc[mf][nf][q]=0.f;

    int r0c = tid >> 2, c0c = tid & 3;
    int r1c = (tid+256) >> 2, c1c = tid & 3;

    auto load_stage = [&](int it, int s){
        int term = it >> 4; int kb = it & 15;
        const __nv_bfloat16* Ap = Aterm[term] + (size_t)bm*ldk + kz + kb*32;
        const __nv_bfloat16* Bp = Bterm[term] + (size_t)bn*ldk + kz + kb*32;
        uint32_t baseA = sb + s*SMEM_STAGE;
        uint32_t baseB = baseA + 10240;
        CP_ASYNC16(baseA + r0c*ROWB + c0c*16, Ap + (size_t)r0c*ldk + c0c*8);
        CP_ASYNC16(baseA + r1c*ROWB + c1c*16, Ap + (size_t)r1c*ldk + c1c*8);
        CP_ASYNC16(baseB + r0c*ROWB + c0c*16, Bp + (size_t)r0c*ldk + c0c*8);
        CP_ASYNC16(baseB + r1c*ROWB + c1c*16, Bp + (size_t)r1c*ldk + c1c*8);
        CP_COMMIT();
    };

    load_stage(0,0);
    load_stage(1,1);

    int arow_base = wm*64 + (lane&7) + ((lane>>3)&1)*8;
    int akoff     = (lane>>4)*16;
    int brow_base = wn*32 + (lane&7) + (lane>>4)*8;
    int bkoff     = ((lane>>3)&1)*16;

    int cur_s = 0, ld_s = 2;
    for (int it=0; it<KITER; it++){
        if (it+1 < KITER) { CP_WAIT(1); } else { CP_WAIT(0); }
        __syncthreads();
        if (it+2 < KITER){
            load_stage(it+2, ld_s);
            ld_s = (ld_s == 2) ? 0 : ld_s + 1;
        }
        uint32_t baseA = sb + cur_s*SMEM_STAGE;
        uint32_t baseB = baseA + 10240;
        #pragma unroll
        for (int ks=0; ks<2; ks++){
            uint32_t a[4][4], b[4][2];
            #pragma unroll
            for (int mf=0; mf<4; mf++){
                uint32_t ad = baseA + (arow_base + mf*16)*ROWB + ks*32 + akoff;
                LDMATRIX_X4(a[mf][0],a[mf][1],a[mf][2],a[mf][3], ad);
            }
            #pragma unroll
            for (int nh=0; nh<2; nh++){
                uint32_t bd = baseB + (brow_base + nh*16)*ROWB + ks*32 + bkoff;
                LDMATRIX_X4(b[nh*2][0],b[nh*2][1],b[nh*2+1][0],b[nh*2+1][1], bd);
            }
            #pragma unroll
            for (int mf=0; mf<4; mf++)
                #pragma unroll
                for (int nf=0; nf<4; nf++)
                    mma16816(acc[mf][nf], a[mf], b[nf]);
        }
        cur_s = (cur_s == 2) ? 0 : cur_s + 1;
    }

    if (!atomic_epi){
        __nv_bfloat16* Lb = LBB(which);
        #pragma unroll
        for (int mf=0; mf<4; mf++){
            int r0 = bm + wm*64 + mf*16 + g;
            #pragma unroll
            for (int nf=0; nf<4; nf++){
                int cc = bn + wn*32 + nf*8 + tig*2;
                float v00 = acc[mf][nf][0], v01 = acc[mf][nf][1];
                float v10 = acc[mf][nf][2], v11 = acc[mf][nf][3];
                *reinterpret_cast<float2*>(C + (size_t)r0*ldc + cc)     = make_float2(v00,v01);
                *reinterpret_cast<float2*>(C + (size_t)(r0+8)*ldc + cc) = make_float2(v10,v11);
                *reinterpret_cast<__nv_bfloat162*>(Lb + (size_t)r0*2048 + cc)     = __floats2bfloat162_rn(v00,v01);
                *reinterpret_cast<__nv_bfloat162*>(Lb + (size_t)(r0+8)*2048 + cc) = __floats2bfloat162_rn(v10,v11);
            }
        }
    } else {
        #pragma unroll
        for (int mf=0; mf<4; mf++){
            int r0 = bm + wm*64 + mf*16 + g;
            #pragma unroll
            for (int nf=0; nf<4; nf++){
                int cc = bn + wn*32 + nf*8 + tig*2;
                atomicAdd(C + (size_t)r0*ldc + cc,       acc[mf][nf][0]);
                atomicAdd(C + (size_t)r0*ldc + cc + 1,   acc[mf][nf][1]);
                atomicAdd(C + (size_t)(r0+8)*ldc + cc,   acc[mf][nf][2]);
                atomicAdd(C + (size_t)(r0+8)*ldc + cc+1, acc[mf][nf][3]);
            }
        }
    }
}

// ==== covariance / variance losses: G = Qsym + P + P^T ====
__global__ void k_covfin(){
    int view = blockIdx.y;
    int i = blockIdx.x, j = threadIdx.x;
    __shared__ float sm[512];
    const float* Q = view ? g_Q2 : g_Q1;
    const float* P = view ? g_P2 : g_P1;
    int bi = i >> 7, bj = j >> 7;
    float qv = (bi <= bj) ? Q[(size_t)i*512 + j] : Q[(size_t)j*512 + i];
    float raw = qv + P[(size_t)i*512 + j] + P[(size_t)j*512 + i];
    float mi = g_csum[view][i] * (1.f/16384.f);
    float mj = g_csum[view][j] * (1.f/16384.f);
    float Cij = (raw - 16384.f*mi*mj) * (1.f/16383.f);
    float c2 = (i==j) ? 0.f : Cij*Cij;
    sm[j]=c2; __syncthreads();
    for (int o=256;o;o>>=1){ if (j<o) sm[j]+=sm[j+o]; __syncthreads(); }
    if (j==0) atomicAdd(&g_misc[view*2+1], sm[0]*(1.f/512.f));
    if (j==i){
        float term = fmaxf(0.f, 0.2f - sqrtf(Cij + 1e-8f));
        atomicAdd(&g_misc[view*2+0], term*(1.f/512.f));
    }
}

// ======================= sinkhorn column pass iter0 (bf16 L, both views) ========
__global__ void k_colpass0(){
    int view = blockIdx.z;
    __shared__ float sm[256];
    int k = blockIdx.x*256 + threadIdx.x;
    size_t b0 = (size_t)blockIdx.y * 128;
    const __nv_bfloat16* L = LBB(view);
    float s = 0.f;
    #pragma unroll 8
    for (int r=0;r<128;r++)
        s += __expf(20.f * __bfloat162float(L[(b0+r)*2048 + k]));
    atomicAdd(&g_t[view][0][k], s);
    sm[threadIdx.x]=s; __syncthreads();
    for (int o=128;o;o>>=1){ if (threadIdx.x<o) sm[threadIdx.x]+=sm[threadIdx.x+o]; __syncthreads(); }
    if (threadIdx.x==0) atomicAdd(&g_S[view], (double)sm[0]);
}

// ========== fused sinkhorn row+col pass, u computed inline — grid (256, 2) ==========
__global__ void __launch_bounds__(256) k_rowcol(int iter){
    int view = blockIdx.y;
    __shared__ float s_u[2048];
    __shared__ float s_v[64];
    const __nv_bfloat16* L = LBB(view);
    int tid = threadIdx.x, lane = tid & 31, wid = tid >> 5;
    // inline u update (replaces k_u launch): iter==1 -> S/(2048 t0); iter==2 -> 1/(2048 t1)
    {
        const float* tp = g_t[view][iter-1];
        float Sf = (iter == 1) ? (float)g_S[view] : 1.f;
        for (int i=tid; i<2048; i+=256){
            s_u[i] = Sf / (2048.f * tp[i]);
        }
    }
    __syncthreads();
    int b0 = blockIdx.x * 64;
    for (int r=0; r<8; r++){
        int b = b0 + wid*8 + r;
        const uint4* Lr = reinterpret_cast<const uint4*>(L + (size_t)b*2048);
        float s = 0.f;
        #pragma unroll
        for (int j=0; j<8; j++){
            int c8 = j*32 + lane;
            uint4 x = Lr[c8];
            const float4* up = reinterpret_cast<const float4*>(&s_u[c8*8]);
            float4 u0 = up[0], u1 = up[1];
            float2 f0 = b2f(x.x), f1 = b2f(x.y), f2 = b2f(x.z), f3 = b2f(x.w);
            s += __expf(20.f*f0.x)*u0.x + __expf(20.f*f0.y)*u0.y
               + __expf(20.f*f1.x)*u0.z + __expf(20.f*f1.y)*u0.w
               + __expf(20.f*f2.x)*u1.x + __expf(20.f*f2.y)*u1.y
               + __expf(20.f*f3.x)*u1.z + __expf(20.f*f3.y)*u1.w;
        }
        #pragma unroll
        for (int o=16;o;o>>=1) s += __shfl_xor_sync(0xFFFFFFFFu, s, o);
        if (lane == 0) s_v[wid*8+r] = 1.f / (16384.f * s);
    }
    __syncthreads();
    float t8[8] = {0.f,0.f,0.f,0.f,0.f,0.f,0.f,0.f};
    const uint4* base = reinterpret_cast<const uint4*>(L) + tid;
    for (int r=0; r<64; r++){
        float vv = s_v[r];
        uint4 x = base[(size_t)(b0+r)*256];
        float2 f0 = b2f(x.x), f1 = b2f(x.y), f2 = b2f(x.z), f3 = b2f(x.w);
        t8[0] += __expf(20.f*f0.x)*vv; t8[1] += __expf(20.f*f0.y)*vv;
        t8[2] += __expf(20.f*f1.x)*vv; t8[3] += __expf(20.f*f1.y)*vv;
        t8[4] += __expf(20.f*f2.x)*vv; t8[5] += __expf(20.f*f2.y)*vv;
        t8[6] += __expf(20.f*f3.x)*vv; t8[7] += __expf(20.f*f3.y)*vv;
    }
    #pragma unroll
    for (int j=0;j<8;j++) atomicAdd(&g_t[view][iter][tid*8+j], t8[j]);
}

// ===== fused final: v + lse/argmax (inline) + CE/avg_probs/acc/hist =====
__global__ void k_final(){
    __shared__ float s_avgp[2048];
    __shared__ float s_us1[2048], s_us2[2048];
    __shared__ float s_v1[16], s_v2[16];
    __shared__ float smf[256]; __shared__ int smi[256];
    __shared__ double smd[256];
    __shared__ float wmx1[8], wmx2[8], wse1[8], wse2[8];
    __shared__ int wix1[8], wix2[8];
    __shared__ float b_ls1, b_ls2; __shared__ int b_am1, b_am2;
    int tid = threadIdx.x, lane = tid & 31, wid = tid >> 5;
    int kbase = tid*8;
    float U1[8],U2[8],LU1[8],LU2[8];
    #pragma unroll
    for (int j=0;j<8;j++){
        float t1 = g_t[0][2][kbase+j];
        float t2 = g_t[1][2][kbase+j];
        float u1 = 1.f / (2048.f * t1);
        float u2 = 1.f / (2048.f * t2);
        U1[j]=u1; U2[j]=u2;
        LU1[j]=logf(u1); LU2[j]=logf(u2);
        s_avgp[kbase+j]=0.f;
        s_us1[kbase+j]=u1; s_us2[kbase+j]=u2;
    }
    __syncthreads();
    int b0 = blockIdx.x*16;
    // phase 1: v for this block's 16 rows (both views) from bf16 L
    #pragma unroll
    for (int rr=0; rr<2; rr++){
        int r = wid*2 + rr;
        int b = b0 + r;
        const uint4* L1r = reinterpret_cast<const uint4*>(g_Lb1 + (size_t)b*2048);
        const uint4* L2r = reinterpret_cast<const uint4*>(g_Lb2 + (size_t)b*2048);
        float s1 = 0.f, s2 = 0.f;
        #pragma unroll
        for (int j=0; j<8; j++){
            int c8 = j*32 + lane;
            uint4 x = L1r[c8];
            const float4* up = reinterpret_cast<const float4*>(&s_us1[c8*8]);
            float4 u0 = up[0], u1 = up[1];
            float2 f0 = b2f(x.x), f1 = b2f(x.y), f2 = b2f(x.z), f3 = b2f(x.w);
            s1 += __expf(20.f*f0.x)*u0.x + __expf(20.f*f0.y)*u0.y
                + __expf(20.f*f1.x)*u0.z + __expf(20.f*f1.y)*u0.w
                + __expf(20.f*f2.x)*u1.x + __expf(20.f*f2.y)*u1.y
                + __expf(20.f*f3.x)*u1.z + __expf(20.f*f3.y)*u1.w;
            uint4 y = L2r[c8];
            const float4* vp = reinterpret_cast<const float4*>(&s_us2[c8*8]);
            float4 v0 = vp[0], v1 = vp[1];
            float2 g0 = b2f(y.x), g1 = b2f(y.y), g2 = b2f(y.z), g3 = b2f(y.w);
            s2 += __expf(20.f*g0.x)*v0.x + __expf(20.f*g0.y)*v0.y
                + __expf(20.f*g1.x)*v0.z + __expf(20.f*g1.y)*v0.w
                + __expf(20.f*g2.x)*v1.x + __expf(20.f*g2.y)*v1.y
                + __expf(20.f*g3.x)*v1.z + __expf(20.f*g3.y)*v1.w;
        }
        #pragma unroll
        for (int o=16;o;o>>=1){
            s1 += __shfl_xor_sync(0xFFFFFFFFu, s1, o);
            s2 += __shfl_xor_sync(0xFFFFFFFFu, s2, o);
        }
        if (lane == 0){ s_v1[r] = s1; s_v2[r] = s2; }
    }
    __syncthreads();
    // phase 2: lse/argmax (inline, replaces k_rowstats) + CE / avg_probs / acc / hist
    double tce1=0.0, tce2=0.0;
    int tacc1=0, tacc2=0;
    for (int r=0;r<16;r++){
        int b = b0 + r;
        const float4* L1r = reinterpret_cast<const float4*>(g_L1 + (size_t)b*2048);
        const float4* L2r = reinterpret_cast<const float4*>(g_L2 + (size_t)b*2048);
        float4 a0=L1r[tid*2], a1=L1r[tid*2+1];
        float4 c0=L2r[tid*2], c1=L2r[tid*2+1];
        float A[8]={a0.x,a0.y,a0.z,a0.w,a1.x,a1.y,a1.z,a1.w};
        float C[8]={c0.x,c0.y,c0.z,c0.w,c1.x,c1.y,c1.z,c1.w};
        // per-row max/argmax + unshifted sum exp(10 L), both views
        float mA=-1e30f, seA=0.f; int iA=kbase;
        float mC=-1e30f, seC=0.f; int iC=kbase;
        float e10A[8], e10C[8];
        #pragma unroll
        for (int j=0;j<8;j++){
            float eA = __expf(10.f*A[j]); e10A[j]=eA; seA += eA;
            float eC = __expf(10.f*C[j]); e10C[j]=eC; seC += eC;
            if (A[j] > mA){ mA = A[j]; iA = kbase+j; }
            if (C[j] > mC){ mC = C[j]; iC = kbase+j; }
        }
        #pragma unroll
        for (int o=16;o;o>>=1){
            float moA = __shfl_xor_sync(0xFFFFFFFFu, mA, o);
            int   ioA = __shfl_xor_sync(0xFFFFFFFFu, iA, o);
            float moC = __shfl_xor_sync(0xFFFFFFFFu, mC, o);
            int   ioC = __shfl_xor_sync(0xFFFFFFFFu, iC, o);
            seA += __shfl_xor_sync(0xFFFFFFFFu, seA, o);
            seC += __shfl_xor_sync(0xFFFFFFFFu, seC, o);
            if (moA > mA || (moA == mA && ioA < iA)){ mA = moA; iA = ioA; }
            if (moC > mC || (moC == mC && ioC < iC)){ mC = moC; iC = ioC; }
        }
        if (lane == 0){ wmx1[wid]=mA; wix1[wid]=iA; wse1[wid]=seA;
                        wmx2[wid]=mC; wix2[wid]=iC; wse2[wid]=seC; }
        __syncthreads();
        if (tid == 0){
            float M1=wmx1[0], M2=wmx2[0]; int I1=wix1[0], I2=wix2[0];
            float S1=wse1[0], S2=wse2[0];
            #pragma unroll
            for (int w=1;w<8;w++){
                S1 += wse1[w]; S2 += wse2[w];
                if (wmx1[w]>M1 || (wmx1[w]==M1 && wix1[w]<I1)){ M1=wmx1[w]; I1=wix1[w]; }
                if (wmx2[w]>M2 || (wmx2[w]==M2 && wix2[w]<I2)){ M2=wmx2[w]; I2=wix2[w]; }
            }
            b_ls1 = logf(S1); b_ls2 = logf(S2);
            b_am1 = I1; b_am2 = I2;
            atomicAdd(&g_hist[I1], 1);
            atomicAdd(&g_hist[I2], 1);
        }
        __syncthreads();
        float ls1 = b_ls1, ls2 = b_ls2;
        int am1 = b_am1, am2 = b_am2;
        float cv1 = 1.f / s_v1[r], cv2 = 1.f / s_v2[r];
        float irs1 = __expf(-ls1), irs2 = __expf(-ls2);
        float sc1=0.f, sc2=0.f;
        float m1=-1e30f, m2=-1e30f; int i1=0, i2=0;
        #pragma unroll
        for (int j=0;j<8;j++){
            float a=A[j], c=C[j];
            float lp1 = 10.f*a - ls1;
            float lp2 = 10.f*c - ls2;
            float t1 = cv1*U1[j]*e10A[j]*e10A[j];
            float t2 = cv2*U2[j]*e10C[j]*e10C[j];
            sc1 += t1*lp2;
            sc2 += t2*lp1;
            s_avgp[kbase+j] += e10A[j]*irs1 + e10C[j]*irs2;
            float g1 = 20.f*a + LU1[j];
            if (g1>m1){ m1=g1; i1=kbase+j; }
            float g2 = 20.f*c + LU2[j];
            if (g2>m2){ m2=g2; i2=kbase+j; }
        }
        tce1 += (double)sc1; tce2 += (double)sc2;
        smf[tid]=m2; smi[tid]=i2; __syncthreads();
        for (int o=128;o;o>>=1){
            if (tid<o && (smf[tid+o]>smf[tid] || (smf[tid+o]==smf[tid] && smi[tid+o]<smi[tid]))){
                smf[tid]=smf[tid+o]; smi[tid]=smi[tid+o];
            }
            __syncthreads();
        }
        if (tid==0 && smi[0]==am1) tacc1++;
        __syncthreads();
        smf[tid]=m1; smi[tid]=i1; __syncthreads();
        for (int o=128;o;o>>=1){
            if (tid<o && (smf[tid+o]>smf[tid] || (smf[tid+o]==smf[tid] && smi[tid+o]<smi[tid]))){
                smf[tid]=smf[tid+o]; smi[tid]=smi[tid+o];
            }
            __syncthreads();
        }
        if (tid==0 && smi[0]==am2) tacc2++;
        __syncthreads();
    }
    smd[tid]=tce1; __syncthreads();
    for (int o=128;o;o>>=1){ if (tid<o) smd[tid]+=smd[tid+o]; __syncthreads(); }
    if (tid==0) atomicAdd(&g_ce[0], smd[0]);
    __syncthreads();
    smd[tid]=tce2; __syncthreads();
    for (int o=128;o;o>>=1){ if (tid<o) smd[tid]+=smd[tid+o]; __syncthreads(); }
    if (tid==0) atomicAdd(&g_ce[1], smd[0]);
    __syncthreads();
    #pragma unroll
    for (int j=0;j<8;j++) atomicAdd(&g_avgp[kbase+j], s_avgp[kbase+j]);
    if (tid==0){ atomicAdd(&g_accc[0], tacc1); atomicAdd(&g_accc[1], tacc2); }
}

__global__ void k_finalize(float* __restrict__ out){
    __shared__ double smd[256];
    int tid = threadIdx.x;
    double sh=0.0, sp=0.0;
    for (int j=0;j<8;j++){
        int k = tid*8 + j;
        double hp = (double)g_hist[k] / 32768.0;
        sh += hp * log(hp + 1e-7);
        double pp = (double)g_avgp[k] / 32768.0;
        sp += pp * log(pp + 1e-7);
    }
    smd[tid]=sh; __syncthreads();
    for (int o=128;o;o>>=1){ if (tid<o) smd[tid]+=smd[tid+o]; __syncthreads(); }
    double H = smd[0]; __syncthreads();
    smd[tid]=sp; __syncthreads();
    for (int o=128;o;o>>=1){ if (tid<o) smd[tid]+=smd[tid+o]; __syncthreads(); }
    double P = smd[0];
    if (tid==0){
        double ce = -0.5 * (g_ce[0]/16384.0 + g_ce[1]/16384.0);
        float lvar = g_misc[0] + g_misc[2];
        float lcov = g_misc[1] + g_misc[3];
        double loss = 15.0*ce + (double)lvar + (double)lcov;
        out[0] = (float)loss;
        out[1] = (float)ce;
        out[2] = lvar;
        out[3] = lcov;
        out[4] = (float)exp(-H);
        out[5] = (float)exp(-P);
        out[6] = 0.5f * ((float)g_accc[0] + (float)g_accc[1]) / 16384.f;
    }
}

// ======================= launch =======================
extern "C" void kernel_launch(void* const* d_in, const int* in_sizes, int n_in,
                              void* d_out, int out_size){
    const float* z1 = (const float*)d_in[0];
    const float* z2 = (const float*)d_in[1];
    const float* W  = (const float*)d_in[2];
    float* out = (float*)d_out;

    cudaFuncSetAttribute(k_mma_all, cudaFuncAttributeMaxDynamicSharedMemorySize, G_SMEM);

    k_wsplit<<<2048,512>>>(W);                      // 0
    k_zero_main<<<1024,256>>>();                    // 1
    k_rownorm<<<Bn,128>>>(z1, 0);                   // 2
    k_rownorm<<<Bn,128>>>(z2, 1);                   // 3
    k_ztrans<<<dim3(16,512),dim3(32,8)>>>(z1, 0);   // 4
    k_ztrans<<<dim3(16,512),dim3(32,8)>>>(z2, 1);   // 5
    k_mma_all<<<5760,256,G_SMEM>>>();               // 6  all 6 GEMMs
    k_covfin<<<dim3(512,2),512>>>();                // 7
    k_colpass0<<<dim3(8,128,2),256>>>();            // 8
    k_rowcol<<<dim3(256,2),256>>>(1);               // 9
    k_rowcol<<<dim3(256,2),256>>>(2);               // 10
    k_final<<<1024,256>>>();                        // 11
    k_finalize<<<1,256>>>(out);                     // 12
}

// round 16
// speedup vs baseline: 1.2162x; 1.0168x over previous
#include <cuda_runtime.h>
#include <cuda_bf16.h>
#include <math.h>
#include <stdint.h>

#define Bn 16384
#define Dn 512
#define Kn 2048

// ======================= PTX helpers (baseline compute_103-safe) =======================
__device__ __forceinline__ uint32_t smem_to_u32(const void* p){
    uint32_t a;
    asm("{ .reg .u64 t; cvta.to.shared.u64 t, %1; cvt.u32.u64 %0, t; }" : "=r"(a) : "l"(p));
    return a;
}
#define CP_ASYNC16(dst, src) \
    asm volatile("cp.async.cg.shared.global [%0], [%1], 16;" :: "r"(dst), "l"(src) : "memory")
#define CP_COMMIT() asm volatile("cp.async.commit_group;" ::: "memory")
#define CP_WAIT(n)  asm volatile("cp.async.wait_group %0;" :: "n"(n) : "memory")
#define LDMATRIX_X4(r0,r1,r2,r3,addr) \
    asm volatile("ldmatrix.sync.aligned.m8n8.x4.shared.b16 {%0,%1,%2,%3}, [%4];" \
        : "=r"(r0),"=r"(r1),"=r"(r2),"=r"(r3) : "r"(addr))

__device__ __forceinline__ void mma16816(float* c, const uint32_t* a, const uint32_t* b){
    asm volatile("mma.sync.aligned.m16n8k16.row.col.f32.bf16.bf16.f32 "
        "{%0,%1,%2,%3}, {%4,%5,%6,%7}, {%8,%9}, {%0,%1,%2,%3};"
        : "+f"(c[0]),"+f"(c[1]),"+f"(c[2]),"+f"(c[3])
        : "r"(a[0]),"r"(a[1]),"r"(a[2]),"r"(a[3]), "r"(b[0]),"r"(b[1]));
}
__device__ __forceinline__ float2 b2f(uint32_t u){
    __nv_bfloat162 b = *reinterpret_cast<__nv_bfloat162*>(&u);
    return __bfloat1622float2(b);
}

// ======================= workspaces =======================
__device__ float g_L1[33554432];                 // [B,K] logits fp32
__device__ float g_L2[33554432];
__device__ __nv_bfloat16 g_Lb1[33554432];        // [B,K] logits bf16 (tolerant readers)
__device__ __nv_bfloat16 g_Lb2[33554432];
__device__ __nv_bfloat16 g_znh1[8388608], g_znl1[8388608];
__device__ __nv_bfloat16 g_znh2[8388608], g_znl2[8388608];
__device__ __nv_bfloat16 g_zth1[8388608], g_ztl1[8388608];
__device__ __nv_bfloat16 g_zth2[8388608], g_ztl2[8388608];
__device__ __nv_bfloat16 g_wh[1048576], g_wl[1048576];
__device__ float g_Q1[262144], g_P1[262144];
__device__ float g_Q2[262144], g_P2[262144];
__device__ float g_csum[2][512];
__device__ float g_t[2][3][2048];
__device__ double g_S[2];
__device__ double g_ce[2];
__device__ float g_avgp[2048];
__device__ int   g_hist[2048];
__device__ int   g_accc[2];
__device__ float g_misc[4];

__device__ const int c_trix[10] = {0,1,1,2,2,2,3,3,3,3};
__device__ const int c_triy[10] = {0,0,1,0,1,2,0,1,2,3};

__device__ __forceinline__ float* LB(int v){ return v ? g_L2 : g_L1; }
__device__ __forceinline__ __nv_bfloat16* LBB(int v){ return v ? g_Lb2 : g_Lb1; }

__device__ __forceinline__ void bsplit(float x, __nv_bfloat16& h, __nv_bfloat16& l){
    h = __float2bfloat16(x);
    l = __float2bfloat16(x - __bfloat162float(h));
}

// ======================= zeroing (every launch — replay idempotency) ===========
__global__ void k_zero_main(){
    int i = blockIdx.x*256 + threadIdx.x;
    g_Q1[i]=0.f; g_P1[i]=0.f; g_Q2[i]=0.f; g_P2[i]=0.f;
    if (i < 12288){ ((float*)g_t)[i]=0.f; }
    if (i < 2048){ g_avgp[i]=0.f; g_hist[i]=0; }
    if (i < 1024){ ((float*)g_csum)[i]=0.f; }
    if (i == 0){
        g_S[0]=0.0; g_S[1]=0.0; g_ce[0]=0.0; g_ce[1]=0.0;
        g_accc[0]=0; g_accc[1]=0;
        g_misc[0]=0.f; g_misc[1]=0.f; g_misc[2]=0.f; g_misc[3]=0.f;
    }
}

// ======================= row l2 normalize -> bf16 hi/lo =======================
__global__ void k_rownorm(const float* __restrict__ z, int view){
    int row = blockIdx.x, t = threadIdx.x;
    __shared__ float sm[128];
    float4 v = reinterpret_cast<const float4*>(z)[(size_t)row*128 + t];
    float s = v.x*v.x + v.y*v.y + v.z*v.z + v.w*v.w;
    sm[t]=s; __syncthreads();
    for (int o=64;o;o>>=1){ if (t<o) sm[t]+=sm[t+o]; __syncthreads(); }
    float inv = 1.f / fmaxf(sqrtf(sm[0]), 1e-12f);
    __nv_bfloat16* H = view ? g_znh2 : g_znh1;
    __nv_bfloat16* L = view ? g_znl2 : g_znl1;
    size_t o = (size_t)row*512 + t*4;
    __nv_bfloat16 h0,h1,h2,h3,l0,l1,l2,l3;
    bsplit(v.x*inv,h0,l0); bsplit(v.y*inv,h1,l1);
    bsplit(v.z*inv,h2,l2); bsplit(v.w*inv,h3,l3);
    __nv_bfloat162* Hp = reinterpret_cast<__nv_bfloat162*>(H + o);
    __nv_bfloat162* Lp = reinterpret_cast<__nv_bfloat162*>(L + o);
    Hp[0] = __nv_bfloat162(h0,h1); Hp[1] = __nv_bfloat162(h2,h3);
    Lp[0] = __nv_bfloat162(l0,l1); Lp[1] = __nv_bfloat162(l2,l3);
}

// ======================= transpose z -> zT bf16 hi/lo, + column sums ============
__global__ void k_ztrans(const float* __restrict__ z, int view){
    __shared__ float t[32][33];
    __shared__ float cs[8][32];
    __nv_bfloat16* TH = view ? g_zth2 : g_zth1;
    __nv_bfloat16* TL = view ? g_ztl2 : g_ztl1;
    int x0 = blockIdx.x*32, y0 = blockIdx.y*32;
    int tx = threadIdx.x, ty = threadIdx.y;
    #pragma unroll
    for (int i=0;i<32;i+=8)
        t[ty+i][tx] = z[(size_t)(y0+ty+i)*512 + x0 + tx];
    __syncthreads();
    cs[ty][tx] = t[ty][tx] + t[ty+8][tx] + t[ty+16][tx] + t[ty+24][tx];
    #pragma unroll
    for (int i=0;i<32;i+=8){
        float v = t[tx][ty+i];
        __nv_bfloat16 h,l; bsplit(v,h,l);
        size_t o = (size_t)(x0+ty+i)*16384 + y0 + tx;
        TH[o]=h; TL[o]=l;
    }
    __syncthreads();
    if (ty==0){
        float s = cs[0][tx]+cs[1][tx]+cs[2][tx]+cs[3][tx]
                + cs[4][tx]+cs[5][tx]+cs[6][tx]+cs[7][tx];
        atomicAdd(&g_csum[view][x0+tx], s);
    }
}

__global__ void k_wsplit(const float* __restrict__ W){
    int i = blockIdx.x*512 + threadIdx.x;
    bsplit(W[i], g_wh[i], g_wl[i]);
}

// ======= mega HMMA GEMM: BM=128,BN=128,BK=64, 3-stage ring, occ 2 =======
// ROWB=144 (128B data + 16 pad): r*144 mod 128 distinct for r=0..7 -> conflict-free
#define ROWB 144
#define STG_A (128*ROWB)          // 18432
#define STG_SZ (2*STG_A)          // 36864
#define G_SMEM (3*STG_SZ)         // 110592

__global__ void __launch_bounds__(256,2) k_mma_all(){
    int idx = blockIdx.x;
    int which, bxx, byy, kzi;
    if (idx < 4096){
        which = idx >> 11;
        int r = idx & 2047;
        bxx = r & 15; byy = r >> 4; kzi = 0;
    } else {
        int i = idx - 4096;
        if (i < 320){ which = 2; }
        else if (i < 832){ which = 3; i -= 320; }
        else if (i < 1152){ which = 4; i -= 832; }
        else { which = 5; i -= 1152; }
        if (which == 2 || which == 4){
            int b = i % 10; bxx = c_trix[b]; byy = c_triy[b]; kzi = i / 10;
        } else {
            bxx = i & 3; byy = (i >> 2) & 3; kzi = i >> 4;
        }
    }

    const __nv_bfloat16 *Ah,*Al,*Bh,*Bl;
    float* C; size_t ldk; int ldc, atomic_epi, KITER;
    if (which == 0){ Ah=g_znh1; Al=g_znl1; Bh=g_wh; Bl=g_wl; C=g_L1; ldk=512; ldc=2048; atomic_epi=0; KITER=24; }
    else if (which == 1){ Ah=g_znh2; Al=g_znl2; Bh=g_wh; Bl=g_wl; C=g_L2; ldk=512; ldc=2048; atomic_epi=0; KITER=24; }
    else if (which == 2){ Ah=g_zth1; Al=g_zth1; Bh=g_zth1; Bl=g_zth1; C=g_Q1; ldk=16384; ldc=512; atomic_epi=1; KITER=8; }
    else if (which == 3){ Ah=g_zth1; Al=g_zth1; Bh=g_ztl1; Bl=g_ztl1; C=g_P1; ldk=16384; ldc=512; atomic_epi=1; KITER=8; }
    else if (which == 4){ Ah=g_zth2; Al=g_zth2; Bh=g_zth2; Bl=g_zth2; C=g_Q2; ldk=16384; ldc=512; atomic_epi=1; KITER=8; }
    else { Ah=g_zth2; Al=g_zth2; Bh=g_ztl2; Bl=g_ztl2; C=g_P2; ldk=16384; ldc=512; atomic_epi=1; KITER=8; }

    extern __shared__ __align__(128) char smem[];
    uint32_t sb = smem_to_u32(smem);

    int tid = threadIdx.x;
    int wid = tid >> 5, lane = tid & 31;
    int wm = wid >> 2, wn = wid & 3;
    int g = lane >> 2, tig = lane & 3;

    int bm = byy*128, bn = bxx*128;
    size_t kz = (size_t)kzi * 512;

    const __nv_bfloat16* Aterm[3] = {Ah, Ah, Al};
    const __nv_bfloat16* Bterm[3] = {Bh, Bl, Bh};

    float acc[4][4][4];
    #pragma unroll
    for (int mf=0;mf<4;mf++)
        #pragma unroll
        for (int nf=0;nf<4;nf++)
            #pragma unroll
            for (int q=0;q<4;q++) acc[mf][nf][q]=0.f;

    int rr0 = tid >> 3, cc0 = tid & 7;   // chunk layout: 128 rows x 8 chunks of 16B

    auto load_stage = [&](int it, int s){
        int term = it >> 3; int kb = it & 7;          // BK=64: 8 kb per term
        const __nv_bfloat16* Ap = Aterm[term] + (size_t)bm*ldk + kz + kb*64;
        const __nv_bfloat16* Bp = Bterm[term] + (size_t)bn*ldk + kz + kb*64;
        uint32_t baseA = sb + s*STG_SZ;
        uint32_t baseB = baseA + STG_A;
        #pragma unroll
        for (int j=0;j<4;j++){
            int r = rr0 + j*32;
            CP_ASYNC16(baseA + r*ROWB + cc0*16, Ap + (size_t)r*ldk + cc0*8);
            CP_ASYNC16(baseB + r*ROWB + cc0*16, Bp + (size_t)r*ldk + cc0*8);
        }
        CP_COMMIT();
    };

    load_stage(0,0);
    load_stage(1,1);

    int arow_base = wm*64 + (lane&7) + ((lane>>3)&1)*8;
    int akoff     = (lane>>4)*16;
    int brow_base = wn*32 + (lane&7) + (lane>>4)*8;
    int bkoff     = ((lane>>3)&1)*16;

    int cur_s = 0, ld_s = 2;
    for (int it=0; it<KITER; it++){
        if (it+1 < KITER) { CP_WAIT(1); } else { CP_WAIT(0); }
        __syncthreads();
        if (it+2 < KITER){
            load_stage(it+2, ld_s);
            ld_s = (ld_s == 2) ? 0 : ld_s + 1;
        }
        uint32_t baseA = sb + cur_s*STG_SZ;
        uint32_t baseB = baseA + STG_A;
        #pragma unroll
        for (int ks=0; ks<4; ks++){
            uint32_t a[4][4], b[4][2];
            #pragma unroll
            for (int mf=0; mf<4; mf++){
                uint32_t ad = baseA + (arow_base + mf*16)*ROWB + ks*32 + akoff;
                LDMATRIX_X4(a[mf][0],a[mf][1],a[mf][2],a[mf][3], ad);
            }
            #pragma unroll
            for (int nh=0; nh<2; nh++){
                uint32_t bd = baseB + (brow_base + nh*16)*ROWB + ks*32 + bkoff;
                LDMATRIX_X4(b[nh*2][0],b[nh*2][1],b[nh*2+1][0],b[nh*2+1][1], bd);
            }
            #pragma unroll
            for (int mf=0; mf<4; mf++)
                #pragma unroll
                for (int nf=0; nf<4; nf++)
                    mma16816(acc[mf][nf], a[mf], b[nf]);
        }
        cur_s = (cur_s == 2) ? 0 : cur_s + 1;
    }

    if (!atomic_epi){
        __nv_bfloat16* Lb = LBB(which);
        #pragma unroll
        for (int mf=0; mf<4; mf++){
            int r0 = bm + wm*64 + mf*16 + g;
            #pragma unroll
            for (int nf=0; nf<4; nf++){
                int cc = bn + wn*32 + nf*8 + tig*2;
                float v00 = acc[mf][nf][0], v01 = acc[mf][nf][1];
                float v10 = acc[mf][nf][2], v11 = acc[mf][nf][3];
                *reinterpret_cast<float2*>(C + (size_t)r0*ldc + cc)     = make_float2(v00,v01);
                *reinterpret_cast<float2*>(C + (size_t)(r0+8)*ldc + cc) = make_float2(v10,v11);
                *reinterpret_cast<__nv_bfloat162*>(Lb + (size_t)r0*2048 + cc)     = __floats2bfloat162_rn(v00,v01);
                *reinterpret_cast<__nv_bfloat162*>(Lb + (size_t)(r0+8)*2048 + cc) = __floats2bfloat162_rn(v10,v11);
            }
        }
    } else {
        #pragma unroll
        for (int mf=0; mf<4; mf++){
            int r0 = bm + wm*64 + mf*16 + g;
            #pragma unroll
            for (int nf=0; nf<4; nf++){
                int cc = bn + wn*32 + nf*8 + tig*2;
                atomicAdd(C + (size_t)r0*ldc + cc,       acc[mf][nf][0]);
                atomicAdd(C + (size_t)r0*ldc + cc + 1,   acc[mf][nf][1]);
                atomicAdd(C + (size_t)(r0+8)*ldc + cc,   acc[mf][nf][2]);
                atomicAdd(C + (size_t)(r0+8)*ldc + cc+1, acc[mf][nf][3]);
            }
        }
    }
}

// ==== covariance / variance losses: G = Qsym + P + P^T ====
__global__ void k_covfin(){
    int view = blockIdx.y;
    int i = blockIdx.x, j = threadIdx.x;
    __shared__ float sm[512];
    const float* Q = view ? g_Q2 : g_Q1;
    const float* P = view ? g_P2 : g_P1;
    int bi = i >> 7, bj = j >> 7;
    float qv = (bi <= bj) ? Q[(size_t)i*512 + j] : Q[(size_t)j*512 + i];
    float raw = qv + P[(size_t)i*512 + j] + P[(size_t)j*512 + i];
    float mi = g_csum[view][i] * (1.f/16384.f);
    float mj = g_csum[view][j] * (1.f/16384.f);
    float Cij = (raw - 16384.f*mi*mj) * (1.f/16383.f);
    float c2 = (i==j) ? 0.f : Cij*Cij;
    sm[j]=c2; __syncthreads();
    for (int o=256;o;o>>=1){ if (j<o) sm[j]+=sm[j+o]; __syncthreads(); }
    if (j==0) atomicAdd(&g_misc[view*2+1], sm[0]*(1.f/512.f));
    if (j==i){
        float term = fmaxf(0.f, 0.2f - sqrtf(Cij + 1e-8f));
        atomicAdd(&g_misc[view*2+0], term*(1.f/512.f));
    }
}

// ======================= sinkhorn column pass iter0 (bf16 L, both views) ========
__global__ void k_colpass0(){
    int view = blockIdx.z;
    __shared__ float sm[256];
    int k = blockIdx.x*256 + threadIdx.x;
    size_t b0 = (size_t)blockIdx.y * 128;
    const __nv_bfloat16* L = LBB(view);
    float s = 0.f;
    #pragma unroll 8
    for (int r=0;r<128;r++)
        s += __expf(20.f * __bfloat162float(L[(b0+r)*2048 + k]));
    atomicAdd(&g_t[view][0][k], s);
    sm[threadIdx.x]=s; __syncthreads();
    for (int o=128;o;o>>=1){ if (threadIdx.x<o) sm[threadIdx.x]+=sm[threadIdx.x+o]; __syncthreads(); }
    if (threadIdx.x==0) atomicAdd(&g_S[view], (double)sm[0]);
}

// ========== fused sinkhorn row+col pass, u computed inline — grid (256, 2) ==========
__global__ void __launch_bounds__(256) k_rowcol(int iter){
    int view = blockIdx.y;
    __shared__ float s_u[2048];
    __shared__ float s_v[64];
    const __nv_bfloat16* L = LBB(view);
    int tid = threadIdx.x, lane = tid & 31, wid = tid >> 5;
    {
        const float* tp = g_t[view][iter-1];
        float Sf = (iter == 1) ? (float)g_S[view] : 1.f;
        for (int i=tid; i<2048; i+=256){
            s_u[i] = Sf / (2048.f * tp[i]);
        }
    }
    __syncthreads();
    int b0 = blockIdx.x * 64;
    for (int r=0; r<8; r++){
        int b = b0 + wid*8 + r;
        const uint4* Lr = reinterpret_cast<const uint4*>(L + (size_t)b*2048);
        float s = 0.f;
        #pragma unroll
        for (int j=0; j<8; j++){
            int c8 = j*32 + lane;
            uint4 x = Lr[c8];
            const float4* up = reinterpret_cast<const float4*>(&s_u[c8*8]);
            float4 u0 = up[0], u1 = up[1];
            float2 f0 = b2f(x.x), f1 = b2f(x.y), f2 = b2f(x.z), f3 = b2f(x.w);
            s += __expf(20.f*f0.x)*u0.x + __expf(20.f*f0.y)*u0.y
               + __expf(20.f*f1.x)*u0.z + __expf(20.f*f1.y)*u0.w
               + __expf(20.f*f2.x)*u1.x + __expf(20.f*f2.y)*u1.y
               + __expf(20.f*f3.x)*u1.z + __expf(20.f*f3.y)*u1.w;
        }
        #pragma unroll
        for (int o=16;o;o>>=1) s += __shfl_xor_sync(0xFFFFFFFFu, s, o);
        if (lane == 0) s_v[wid*8+r] = 1.f / (16384.f * s);
    }
    __syncthreads();
    float t8[8] = {0.f,0.f,0.f,0.f,0.f,0.f,0.f,0.f};
    const uint4* base = reinterpret_cast<const uint4*>(L) + tid;
    for (int r=0; r<64; r++){
        float vv = s_v[r];
        uint4 x = base[(size_t)(b0+r)*256];
        float2 f0 = b2f(x.x), f1 = b2f(x.y), f2 = b2f(x.z), f3 = b2f(x.w);
        t8[0] += __expf(20.f*f0.x)*vv; t8[1] += __expf(20.f*f0.y)*vv;
        t8[2] += __expf(20.f*f1.x)*vv; t8[3] += __expf(20.f*f1.y)*vv;
        t8[4] += __expf(20.f*f2.x)*vv; t8[5] += __expf(20.f*f2.y)*vv;
        t8[6] += __expf(20.f*f3.x)*vv; t8[7] += __expf(20.f*f3.y)*vv;
    }
    #pragma unroll
    for (int j=0;j<8;j++) atomicAdd(&g_t[view][iter][tid*8+j], t8[j]);
}

// ===== fused final: v + lse/argmax (inline) + CE/avg_probs/acc/hist =====
__global__ void k_final(){
    __shared__ float s_avgp[2048];
    __shared__ float s_us1[2048], s_us2[2048];
    __shared__ float s_v1[16], s_v2[16];
    __shared__ float smf[256]; __shared__ int smi[256];
    __shared__ double smd[256];
    __shared__ float wmx1[8], wmx2[8], wse1[8], wse2[8];
    __shared__ int wix1[8], wix2[8];
    __shared__ float b_ls1, b_ls2; __shared__ int b_am1, b_am2;
    int tid = threadIdx.x, lane = tid & 31, wid = tid >> 5;
    int kbase = tid*8;
    float U1[8],U2[8],LU1[8],LU2[8];
    #pragma unroll
    for (int j=0;j<8;j++){
        float t1 = g_t[0][2][kbase+j];
        float t2 = g_t[1][2][kbase+j];
        float u1 = 1.f / (2048.f * t1);
        float u2 = 1.f / (2048.f * t2);
        U1[j]=u1; U2[j]=u2;
        LU1[j]=logf(u1); LU2[j]=logf(u2);
        s_avgp[kbase+j]=0.f;
        s_us1[kbase+j]=u1; s_us2[kbase+j]=u2;
    }
    __syncthreads();
    int b0 = blockIdx.x*16;
    #pragma unroll
    for (int rr=0; rr<2; rr++){
        int r = wid*2 + rr;
        int b = b0 + r;
        const uint4* L1r = reinterpret_cast<const uint4*>(g_Lb1 + (size_t)b*2048);
        const uint4* L2r = reinterpret_cast<const uint4*>(g_Lb2 + (size_t)b*2048);
        float s1 = 0.f, s2 = 0.f;
        #pragma unroll
        for (int j=0; j<8; j++){
            int c8 = j*32 + lane;
            uint4 x = L1r[c8];
            const float4* up = reinterpret_cast<const float4*>(&s_us1[c8*8]);
            float4 u0 = up[0], u1 = up[1];
            float2 f0 = b2f(x.x), f1 = b2f(x.y), f2 = b2f(x.z), f3 = b2f(x.w);
            s1 += __expf(20.f*f0.x)*u0.x + __expf(20.f*f0.y)*u0.y
                + __expf(20.f*f1.x)*u0.z + __expf(20.f*f1.y)*u0.w
                + __expf(20.f*f2.x)*u1.x + __expf(20.f*f2.y)*u1.y
                + __expf(20.f*f3.x)*u1.z + __expf(20.f*f3.y)*u1.w;
            uint4 y = L2r[c8];
            const float4* vp = reinterpret_cast<const float4*>(&s_us2[c8*8]);
            float4 v0 = vp[0], v1 = vp[1];
            float2 g0 = b2f(y.x), g1 = b2f(y.y), g2 = b2f(y.z), g3 = b2f(y.w);
            s2 += __expf(20.f*g0.x)*v0.x + __expf(20.f*g0.y)*v0.y
                + __expf(20.f*g1.x)*v0.z + __expf(20.f*g1.y)*v0.w
                + __expf(20.f*g2.x)*v1.x + __expf(20.f*g2.y)*v1.y
                + __expf(20.f*g3.x)*v1.z + __expf(20.f*g3.y)*v1.w;
        }
        #pragma unroll
        for (int o=16;o;o>>=1){
            s1 += __shfl_xor_sync(0xFFFFFFFFu, s1, o);
            s2 += __shfl_xor_sync(0xFFFFFFFFu, s2, o);
        }
        if (lane == 0){ s_v1[r] = s1; s_v2[r] = s2; }
    }
    __syncthreads();
    double tce1=0.0, tce2=0.0;
    int tacc1=0, tacc2=0;
    for (int r=0;r<16;r++){
        int b = b0 + r;
        const float4* L1r = reinterpret_cast<const float4*>(g_L1 + (size_t)b*2048);
        const float4* L2r = reinterpret_cast<const float4*>(g_L2 + (size_t)b*2048);
        float4 a0=L1r[tid*2], a1=L1r[tid*2+1];
        float4 c0=L2r[tid*2], c1=L2r[tid*2+1];
        float A[8]={a0.x,a0.y,a0.z,a0.w,a1.x,a1.y,a1.z,a1.w};
        float C[8]={c0.x,c0.y,c0.z,c0.w,c1.x,c1.y,c1.z,c1.w};
        float mA=-1e30f, seA=0.f; int iA=kbase;
        float mC=-1e30f, seC=0.f; int iC=kbase;
        float e10A[8], e10C[8];
        #pragma unroll
        for (int j=0;j<8;j++){
            float eA = __expf(10.f*A[j]); e10A[j]=eA; seA += eA;
            float eC = __expf(10.f*C[j]); e10C[j]=eC; seC += eC;
            if (A[j] > mA){ mA = A[j]; iA = kbase+j; }
            if (C[j] > mC){ mC = C[j]; iC = kbase+j; }
        }
        #pragma unroll
        for (int o=16;o;o>>=1){
            float moA = __shfl_xor_sync(0xFFFFFFFFu, mA, o);
            int   ioA = __shfl_xor_sync(0xFFFFFFFFu, iA, o);
            float moC = __shfl_xor_sync(0xFFFFFFFFu, mC, o);
            int   ioC = __shfl_xor_sync(0xFFFFFFFFu, iC, o);
            seA += __shfl_xor_sync(0xFFFFFFFFu, seA, o);
            seC += __shfl_xor_sync(0xFFFFFFFFu, seC, o);
            if (moA > mA || (moA == mA && ioA < iA)){ mA = moA; iA = ioA; }
            if (moC > mC || (moC == mC && ioC < iC)){ mC = moC; iC = ioC; }
        }
        if (lane == 0){ wmx1[wid]=mA; wix1[wid]=iA; wse1[wid]=seA;
                        wmx2[wid]=mC; wix2[wid]=iC; wse2[wid]=seC; }
        __syncthreads();
        if (tid == 0){
            float M1=wmx1[0], M2=wmx2[0]; int I1=wix1[0], I2=wix2[0];
            float S1=wse1[0], S2=wse2[0];
            #pragma unroll
            for (int w=1;w<8;w++){
                S1 += wse1[w]; S2 += wse2[w];
                if (wmx1[w]>M1 || (wmx1[w]==M1 && wix1[w]<I1)){ M1=wmx1[w]; I1=wix1[w]; }
                if (wmx2[w]>M2 || (wmx2[w]==M2 && wix2[w]<I2)){ M2=wmx2[w]; I2=wix2[w]; }
            }
            b_ls1 = logf(S1); b_ls2 = logf(S2);
            b_am1 = I1; b_am2 = I2;
            atomicAdd(&g_hist[I1], 1);
            atomicAdd(&g_hist[I2], 1);
        }
        __syncthreads();
        float ls1 = b_ls1, ls2 = b_ls2;
        int am1 = b_am1, am2 = b_am2;
        float cv1 = 1.f / s_v1[r], cv2 = 1.f / s_v2[r];
        float irs1 = __expf(-ls1), irs2 = __expf(-ls2);
        float sc1=0.f, sc2=0.f;
        float m1=-1e30f, m2=-1e30f; int i1=0, i2=0;
        #pragma unroll
        for (int j=0;j<8;j++){
            float a=A[j], c=C[j];
            float lp1 = 10.f*a - ls1;
            float lp2 = 10.f*c - ls2;
            float t1 = cv1*U1[j]*e10A[j]*e10A[j];
            float t2 = cv2*U2[j]*e10C[j]*e10C[j];
            sc1 += t1*lp2;
            sc2 += t2*lp1;
            s_avgp[kbase+j] += e10A[j]*irs1 + e10C[j]*irs2;
            float g1 = 20.f*a + LU1[j];
            if (g1>m1){ m1=g1; i1=kbase+j; }
            float g2 = 20.f*c + LU2[j];
            if (g2>m2){ m2=g2; i2=kbase+j; }
        }
        tce1 += (double)sc1; tce2 += (double)sc2;
        smf[tid]=m2; smi[tid]=i2; __syncthreads();
        for (int o=128;o;o>>=1){
            if (tid<o && (smf[tid+o]>smf[tid] || (smf[tid+o]==smf[tid] && smi[tid+o]<smi[tid]))){
                smf[tid]=smf[tid+o]; smi[tid]=smi[tid+o];
            }
            __syncthreads();
        }
        if (tid==0 && smi[0]==am1) tacc1++;
        __syncthreads();
        smf[tid]=m1; smi[tid]=i1; __syncthreads();
        for (int o=128;o;o>>=1){
            if (tid<o && (smf[tid+o]>smf[tid] || (smf[tid+o]==smf[tid] && smi[tid+o]<smi[tid]))){
                smf[tid]=smf[tid+o]; smi[tid]=smi[tid+o];
            }
            __syncthreads();
        }
        if (tid==0 && smi[0]==am2) tacc2++;
        __syncthreads();
    }
    smd[tid]=tce1; __syncthreads();
    for (int o=128;o;o>>=1){ if (tid<o) smd[tid]+=smd[tid+o]; __syncthreads(); }
    if (tid==0) atomicAdd(&g_ce[0], smd[0]);
    __syncthreads();
    smd[tid]=tce2; __syncthreads();
    for (int o=128;o;o>>=1){ if (tid<o) smd[tid]+=smd[tid+o]; __syncthreads(); }
    if (tid==0) atomicAdd(&g_ce[1], smd[0]);
    __syncthreads();
    #pragma unroll
    for (int j=0;j<8;j++) atomicAdd(&g_avgp[kbase+j], s_avgp[kbase+j]);
    if (tid==0){ atomicAdd(&g_accc[0], tacc1); atomicAdd(&g_accc[1], tacc2); }
}

__global__ void k_finalize(float* __restrict__ out){
    __shared__ double smd[256];
    int tid = threadIdx.x;
    double sh=0.0, sp=0.0;
    for (int j=0;j<8;j++){
        int k = tid*8 + j;
        double hp = (double)g_hist[k] / 32768.0;
        sh += hp * log(hp + 1e-7);
        double pp = (double)g_avgp[k] / 32768.0;
        sp += pp * log(pp + 1e-7);
    }
    smd[tid]=sh; __syncthreads();
    for (int o=128;o;o>>=1){ if (tid<o) smd[tid]+=smd[tid+o]; __syncthreads(); }
    double H = smd[0]; __syncthreads();
    smd[tid]=sp; __syncthreads();
    for (int o=128;o;o>>=1){ if (tid<o) smd[tid]+=smd[tid+o]; __syncthreads(); }
    double P = smd[0];
    if (tid==0){
        double ce = -0.5 * (g_ce[0]/16384.0 + g_ce[1]/16384.0);
        float lvar = g_misc[0] + g_misc[2];
        float lcov = g_misc[1] + g_misc[3];
        double loss = 15.0*ce + (double)lvar + (double)lcov;
        out[0] = (float)loss;
        out[1] = (float)ce;
        out[2] = lvar;
        out[3] = lcov;
        out[4] = (float)exp(-H);
        out[5] = (float)exp(-P);
        out[6] = 0.5f * ((float)g_accc[0] + (float)g_accc[1]) / 16384.f;
    }
}

// ======================= launch =======================
extern "C" void kernel_launch(void* const* d_in, const int* in_sizes, int n_in,
                              void* d_out, int out_size){
    const float* z1 = (const float*)d_in[0];
    const float* z2 = (const float*)d_in[1];
    const float* W  = (const float*)d_in[2];
    float* out = (float*)d_out;

    cudaFuncSetAttribute(k_mma_all, cudaFuncAttributeMaxDynamicSharedMemorySize, G_SMEM);

    k_wsplit<<<2048,512>>>(W);                      // 0
    k_zero_main<<<1024,256>>>();                    // 1
    k_rownorm<<<Bn,128>>>(z1, 0);                   // 2
    k_rownorm<<<Bn,128>>>(z2, 1);                   // 3
    k_ztrans<<<dim3(16,512),dim3(32,8)>>>(z1, 0);   // 4
    k_ztrans<<<dim3(16,512),dim3(32,8)>>>(z2, 1);   // 5
    k_mma_all<<<5760,256,G_SMEM>>>();               // 6  all 6 GEMMs (BK=64)
    k_covfin<<<dim3(512,2),512>>>();                // 7
    k_colpass0<<<dim3(8,128,2),256>>>();            // 8
    k_rowcol<<<dim3(256,2),256>>>(1);               // 9
    k_rowcol<<<dim3(256,2),256>>>(2);               // 10
    k_final<<<1024,256>>>();                        // 11
    k_finalize<<<1,256>>>(out);                     // 12
}

// round 17
// speedup vs baseline: 1.3600x; 1.1183x over previous
#include <cuda_runtime.h>
#include <cuda_bf16.h>
#include <math.h>
#include <stdint.h>

#define Bn 16384
#define Dn 512
#define Kn 2048

// ======================= PTX helpers (baseline compute_103-safe) =======================
__device__ __forceinline__ uint32_t smem_to_u32(const void* p){
    uint32_t a;
    asm("{ .reg .u64 t; cvta.to.shared.u64 t, %1; cvt.u32.u64 %0, t; }" : "=r"(a) : "l"(p));
    return a;
}
#define CP_ASYNC16(dst, src) \
    asm volatile("cp.async.cg.shared.global [%0], [%1], 16;" :: "r"(dst), "l"(src) : "memory")
#define CP_COMMIT() asm volatile("cp.async.commit_group;" ::: "memory")
#define CP_WAIT(n)  asm volatile("cp.async.wait_group %0;" :: "n"(n) : "memory")
#define LDMATRIX_X4(r0,r1,r2,r3,addr) \
    asm volatile("ldmatrix.sync.aligned.m8n8.x4.shared.b16 {%0,%1,%2,%3}, [%4];" \
        : "=r"(r0),"=r"(r1),"=r"(r2),"=r"(r3) : "r"(addr))

__device__ __forceinline__ void mma16816(float* c, const uint32_t* a, const uint32_t* b){
    asm volatile("mma.sync.aligned.m16n8k16.row.col.f32.bf16.bf16.f32 "
        "{%0,%1,%2,%3}, {%4,%5,%6,%7}, {%8,%9}, {%0,%1,%2,%3};"
        : "+f"(c[0]),"+f"(c[1]),"+f"(c[2]),"+f"(c[3])
        : "r"(a[0]),"r"(a[1]),"r"(a[2]),"r"(a[3]), "r"(b[0]),"r"(b[1]));
}
__device__ __forceinline__ float2 b2f(uint32_t u){
    __nv_bfloat162 b = *reinterpret_cast<__nv_bfloat162*>(&u);
    return __bfloat1622float2(b);
}

// ======================= workspaces =======================
__device__ float g_L1[33554432];                 // [B,K] logits fp32
__device__ float g_L2[33554432];
__device__ __nv_bfloat16 g_Lb1[33554432];        // [B,K] logits bf16 (tolerant readers)
__device__ __nv_bfloat16 g_Lb2[33554432];
__device__ __nv_bfloat16 g_znh1[8388608], g_znl1[8388608];
__device__ __nv_bfloat16 g_znh2[8388608], g_znl2[8388608];
__device__ __nv_bfloat16 g_zth1[8388608], g_ztl1[8388608];
__device__ __nv_bfloat16 g_zth2[8388608], g_ztl2[8388608];
__device__ __nv_bfloat16 g_wh[1048576], g_wl[1048576];
__device__ float g_Q1[262144], g_P1[262144];
__device__ float g_Q2[262144], g_P2[262144];
__device__ float g_csum[2][512];
__device__ float g_t[2][3][2048];
__device__ double g_S[2];
__device__ double g_ce[2];
__device__ float g_avgp[2048];
__device__ int   g_hist[2048];
__device__ int   g_accc[2];
__device__ float g_misc[4];

__device__ const int c_trix[10] = {0,1,1,2,2,2,3,3,3,3};
__device__ const int c_triy[10] = {0,0,1,0,1,2,0,1,2,3};

__device__ __forceinline__ float* LB(int v){ return v ? g_L2 : g_L1; }
__device__ __forceinline__ __nv_bfloat16* LBB(int v){ return v ? g_Lb2 : g_Lb1; }

__device__ __forceinline__ void bsplit(float x, __nv_bfloat16& h, __nv_bfloat16& l){
    h = __float2bfloat16(x);
    l = __float2bfloat16(x - __bfloat162float(h));
}

// ======================= zeroing (every launch — replay idempotency) ===========
__global__ void k_zero_main(){
    int i = blockIdx.x*256 + threadIdx.x;
    g_Q1[i]=0.f; g_P1[i]=0.f; g_Q2[i]=0.f; g_P2[i]=0.f;
    if (i < 12288){ ((float*)g_t)[i]=0.f; }
    if (i < 2048){ g_avgp[i]=0.f; g_hist[i]=0; }
    if (i < 1024){ ((float*)g_csum)[i]=0.f; }
    if (i == 0){
        g_S[0]=0.0; g_S[1]=0.0; g_ce[0]=0.0; g_ce[1]=0.0;
        g_accc[0]=0; g_accc[1]=0;
        g_misc[0]=0.f; g_misc[1]=0.f; g_misc[2]=0.f; g_misc[3]=0.f;
    }
}

// ======================= row l2 normalize -> bf16 hi/lo =======================
__global__ void k_rownorm(const float* __restrict__ z, int view){
    int row = blockIdx.x, t = threadIdx.x;
    __shared__ float sm[128];
    float4 v = reinterpret_cast<const float4*>(z)[(size_t)row*128 + t];
    float s = v.x*v.x + v.y*v.y + v.z*v.z + v.w*v.w;
    sm[t]=s; __syncthreads();
    for (int o=64;o;o>>=1){ if (t<o) sm[t]+=sm[t+o]; __syncthreads(); }
    float inv = 1.f / fmaxf(sqrtf(sm[0]), 1e-12f);
    __nv_bfloat16* H = view ? g_znh2 : g_znh1;
    __nv_bfloat16* L = view ? g_znl2 : g_znl1;
    size_t o = (size_t)row*512 + t*4;
    __nv_bfloat16 h0,h1,h2,h3,l0,l1,l2,l3;
    bsplit(v.x*inv,h0,l0); bsplit(v.y*inv,h1,l1);
    bsplit(v.z*inv,h2,l2); bsplit(v.w*inv,h3,l3);
    __nv_bfloat162* Hp = reinterpret_cast<__nv_bfloat162*>(H + o);
    __nv_bfloat162* Lp = reinterpret_cast<__nv_bfloat162*>(L + o);
    Hp[0] = __nv_bfloat162(h0,h1); Hp[1] = __nv_bfloat162(h2,h3);
    Lp[0] = __nv_bfloat162(l0,l1); Lp[1] = __nv_bfloat162(l2,l3);
}

// ======================= transpose z -> zT bf16 hi/lo, + column sums ============
__global__ void k_ztrans(const float* __restrict__ z, int view){
    __shared__ float t[32][33];
    __shared__ float cs[8][32];
    __nv_bfloat16* TH = view ? g_zth2 : g_zth1;
    __nv_bfloat16* TL = view ? g_ztl2 : g_ztl1;
    int x0 = blockIdx.x*32, y0 = blockIdx.y*32;
    int tx = threadIdx.x, ty = threadIdx.y;
    #pragma unroll
    for (int i=0;i<32;i+=8)
        t[ty+i][tx] = z[(size_t)(y0+ty+i)*512 + x0 + tx];
    __syncthreads();
    cs[ty][tx] = t[ty][tx] + t[ty+8][tx] + t[ty+16][tx] + t[ty+24][tx];
    #pragma unroll
    for (int i=0;i<32;i+=8){
        float v = t[tx][ty+i];
        __nv_bfloat16 h,l; bsplit(v,h,l);
        size_t o = (size_t)(x0+ty+i)*16384 + y0 + tx;
        TH[o]=h; TL[o]=l;
    }
    __syncthreads();
    if (ty==0){
        float s = cs[0][tx]+cs[1][tx]+cs[2][tx]+cs[3][tx]
                + cs[4][tx]+cs[5][tx]+cs[6][tx]+cs[7][tx];
        atomicAdd(&g_csum[view][x0+tx], s);
    }
}

__global__ void k_wsplit(const float* __restrict__ W){
    int i = blockIdx.x*512 + threadIdx.x;
    bsplit(W[i], g_wh[i], g_wl[i]);
}

// ======= mega HMMA GEMM: BM=128,BN=128,BK=64, 3-stage ring, occ 2 =======
#define ROWB 144
#define STG_A (128*ROWB)          // 18432
#define STG_SZ (2*STG_A)          // 36864
#define G_SMEM (3*STG_SZ)         // 110592

__global__ void __launch_bounds__(256,2) k_mma_all(){
    int idx = blockIdx.x;
    int which, bxx, byy, kzi;
    if (idx < 4096){
        which = idx >> 11;
        int r = idx & 2047;
        bxx = r & 15; byy = r >> 4; kzi = 0;
    } else {
        int i = idx - 4096;
        if (i < 320){ which = 2; }
        else if (i < 832){ which = 3; i -= 320; }
        else if (i < 1152){ which = 4; i -= 832; }
        else { which = 5; i -= 1152; }
        if (which == 2 || which == 4){
            int b = i % 10; bxx = c_trix[b]; byy = c_triy[b]; kzi = i / 10;
        } else {
            bxx = i & 3; byy = (i >> 2) & 3; kzi = i >> 4;
        }
    }

    const __nv_bfloat16 *Ah,*Al,*Bh,*Bl;
    float* C; size_t ldk; int ldc, atomic_epi, KITER;
    if (which == 0){ Ah=g_znh1; Al=g_znl1; Bh=g_wh; Bl=g_wl; C=g_L1; ldk=512; ldc=2048; atomic_epi=0; KITER=24; }
    else if (which == 1){ Ah=g_znh2; Al=g_znl2; Bh=g_wh; Bl=g_wl; C=g_L2; ldk=512; ldc=2048; atomic_epi=0; KITER=24; }
    else if (which == 2){ Ah=g_zth1; Al=g_zth1; Bh=g_zth1; Bl=g_zth1; C=g_Q1; ldk=16384; ldc=512; atomic_epi=1; KITER=8; }
    else if (which == 3){ Ah=g_zth1; Al=g_zth1; Bh=g_ztl1; Bl=g_ztl1; C=g_P1; ldk=16384; ldc=512; atomic_epi=1; KITER=8; }
    else if (which == 4){ Ah=g_zth2; Al=g_zth2; Bh=g_zth2; Bl=g_zth2; C=g_Q2; ldk=16384; ldc=512; atomic_epi=1; KITER=8; }
    else { Ah=g_zth2; Al=g_zth2; Bh=g_ztl2; Bl=g_ztl2; C=g_P2; ldk=16384; ldc=512; atomic_epi=1; KITER=8; }

    extern __shared__ __align__(128) char smem[];
    uint32_t sb = smem_to_u32(smem);

    int tid = threadIdx.x;
    int wid = tid >> 5, lane = tid & 31;
    int wm = wid >> 2, wn = wid & 3;
    int g = lane >> 2, tig = lane & 3;

    int bm = byy*128, bn = bxx*128;
    size_t kz = (size_t)kzi * 512;

    const __nv_bfloat16* Aterm[3] = {Ah, Ah, Al};
    const __nv_bfloat16* Bterm[3] = {Bh, Bl, Bh};

    float acc[4][4][4];
    #pragma unroll
    for (int mf=0;mf<4;mf++)
        #pragma unroll
        for (int nf=0;nf<4;nf++)
            #pragma unroll
            for (int q=0;q<4;q++) acc[mf][nf][q]=0.f;

    int rr0 = tid >> 3, cc0 = tid & 7;

    auto load_stage = [&](int it, int s){
        int term = it >> 3; int kb = it & 7;
        const __nv_bfloat16* Ap = Aterm[term] + (size_t)bm*ldk + kz + kb*64;
        const __nv_bfloat16* Bp = Bterm[term] + (size_t)bn*ldk + kz + kb*64;
        uint32_t baseA = sb + s*STG_SZ;
        uint32_t baseB = baseA + STG_A;
        #pragma unroll
        for (int j=0;j<4;j++){
            int r = rr0 + j*32;
            CP_ASYNC16(baseA + r*ROWB + cc0*16, Ap + (size_t)r*ldk + cc0*8);
            CP_ASYNC16(baseB + r*ROWB + cc0*16, Bp + (size_t)r*ldk + cc0*8);
        }
        CP_COMMIT();
    };

    load_stage(0,0);
    load_stage(1,1);

    int arow_base = wm*64 + (lane&7) + ((lane>>3)&1)*8;
    int akoff     = (lane>>4)*16;
    int brow_base = wn*32 + (lane&7) + (lane>>4)*8;
    int bkoff     = ((lane>>3)&1)*16;

    int cur_s = 0, ld_s = 2;
    for (int it=0; it<KITER; it++){
        if (it+1 < KITER) { CP_WAIT(1); } else { CP_WAIT(0); }
        __syncthreads();
        if (it+2 < KITER){
            load_stage(it+2, ld_s);
            ld_s = (ld_s == 2) ? 0 : ld_s + 1;
        }
        uint32_t baseA = sb + cur_s*STG_SZ;
        uint32_t baseB = baseA + STG_A;
        #pragma unroll
        for (int ks=0; ks<4; ks++){
            uint32_t a[4][4], b[4][2];
            #pragma unroll
            for (int mf=0; mf<4; mf++){
                uint32_t ad = baseA + (arow_base + mf*16)*ROWB + ks*32 + akoff;
                LDMATRIX_X4(a[mf][0],a[mf][1],a[mf][2],a[mf][3], ad);
            }
            #pragma unroll
            for (int nh=0; nh<2; nh++){
                uint32_t bd = baseB + (brow_base + nh*16)*ROWB + ks*32 + bkoff;
                LDMATRIX_X4(b[nh*2][0],b[nh*2][1],b[nh*2+1][0],b[nh*2+1][1], bd);
            }
            #pragma unroll
            for (int mf=0; mf<4; mf++)
                #pragma unroll
                for (int nf=0; nf<4; nf++)
                    mma16816(acc[mf][nf], a[mf], b[nf]);
        }
        cur_s = (cur_s == 2) ? 0 : cur_s + 1;
    }

    if (!atomic_epi){
        __nv_bfloat16* Lb = LBB(which);
        #pragma unroll
        for (int mf=0; mf<4; mf++){
            int r0 = bm + wm*64 + mf*16 + g;
            #pragma unroll
            for (int nf=0; nf<4; nf++){
                int cc = bn + wn*32 + nf*8 + tig*2;
                float v00 = acc[mf][nf][0], v01 = acc[mf][nf][1];
                float v10 = acc[mf][nf][2], v11 = acc[mf][nf][3];
                *reinterpret_cast<float2*>(C + (size_t)r0*ldc + cc)     = make_float2(v00,v01);
                *reinterpret_cast<float2*>(C + (size_t)(r0+8)*ldc + cc) = make_float2(v10,v11);
                *reinterpret_cast<__nv_bfloat162*>(Lb + (size_t)r0*2048 + cc)     = __floats2bfloat162_rn(v00,v01);
                *reinterpret_cast<__nv_bfloat162*>(Lb + (size_t)(r0+8)*2048 + cc) = __floats2bfloat162_rn(v10,v11);
            }
        }
    } else {
        #pragma unroll
        for (int mf=0; mf<4; mf++){
            int r0 = bm + wm*64 + mf*16 + g;
            #pragma unroll
            for (int nf=0; nf<4; nf++){
                int cc = bn + wn*32 + nf*8 + tig*2;
                atomicAdd(C + (size_t)r0*ldc + cc,       acc[mf][nf][0]);
                atomicAdd(C + (size_t)r0*ldc + cc + 1,   acc[mf][nf][1]);
                atomicAdd(C + (size_t)(r0+8)*ldc + cc,   acc[mf][nf][2]);
                atomicAdd(C + (size_t)(r0+8)*ldc + cc+1, acc[mf][nf][3]);
            }
        }
    }
}

// ==== covariance / variance losses: G = Qsym + P + P^T ====
__global__ void k_covfin(){
    int view = blockIdx.y;
    int i = blockIdx.x, j = threadIdx.x;
    __shared__ float sm[512];
    const float* Q = view ? g_Q2 : g_Q1;
    const float* P = view ? g_P2 : g_P1;
    int bi = i >> 7, bj = j >> 7;
    float qv = (bi <= bj) ? Q[(size_t)i*512 + j] : Q[(size_t)j*512 + i];
    float raw = qv + P[(size_t)i*512 + j] + P[(size_t)j*512 + i];
    float mi = g_csum[view][i] * (1.f/16384.f);
    float mj = g_csum[view][j] * (1.f/16384.f);
    float Cij = (raw - 16384.f*mi*mj) * (1.f/16383.f);
    float c2 = (i==j) ? 0.f : Cij*Cij;
    sm[j]=c2; __syncthreads();
    for (int o=256;o;o>>=1){ if (j<o) sm[j]+=sm[j+o]; __syncthreads(); }
    if (j==0) atomicAdd(&g_misc[view*2+1], sm[0]*(1.f/512.f));
    if (j==i){
        float term = fmaxf(0.f, 0.2f - sqrtf(Cij + 1e-8f));
        atomicAdd(&g_misc[view*2+0], term*(1.f/512.f));
    }
}

// ======================= sinkhorn column pass iter0 (bf16 L, both views) ========
__global__ void k_colpass0(){
    int view = blockIdx.z;
    __shared__ float sm[256];
    int k = blockIdx.x*256 + threadIdx.x;
    size_t b0 = (size_t)blockIdx.y * 128;
    const __nv_bfloat16* L = LBB(view);
    float s = 0.f;
    #pragma unroll 8
    for (int r=0;r<128;r++)
        s += __expf(20.f * __bfloat162float(L[(b0+r)*2048 + k]));
    atomicAdd(&g_t[view][0][k], s);
    sm[threadIdx.x]=s; __syncthreads();
    for (int o=128;o;o>>=1){ if (threadIdx.x<o) sm[threadIdx.x]+=sm[threadIdx.x+o]; __syncthreads(); }
    if (threadIdx.x==0) atomicAdd(&g_S[view], (double)sm[0]);
}

// ========== fused sinkhorn row+col pass, u computed inline — grid (256, 2) ==========
__global__ void __launch_bounds__(256) k_rowcol(int iter){
    int view = blockIdx.y;
    __shared__ float s_u[2048];
    __shared__ float s_v[64];
    const __nv_bfloat16* L = LBB(view);
    int tid = threadIdx.x, lane = tid & 31, wid = tid >> 5;
    {
        const float* tp = g_t[view][iter-1];
        float Sf = (iter == 1) ? (float)g_S[view] : 1.f;
        for (int i=tid; i<2048; i+=256){
            s_u[i] = Sf / (2048.f * tp[i]);
        }
    }
    __syncthreads();
    int b0 = blockIdx.x * 64;
    for (int r=0; r<8; r++){
        int b = b0 + wid*8 + r;
        const uint4* Lr = reinterpret_cast<const uint4*>(L + (size_t)b*2048);
        float s = 0.f;
        #pragma unroll
        for (int j=0; j<8; j++){
            int c8 = j*32 + lane;
            uint4 x = Lr[c8];
            const float4* up = reinterpret_cast<const float4*>(&s_u[c8*8]);
            float4 u0 = up[0], u1 = up[1];
            float2 f0 = b2f(x.x), f1 = b2f(x.y), f2 = b2f(x.z), f3 = b2f(x.w);
            s += __expf(20.f*f0.x)*u0.x + __expf(20.f*f0.y)*u0.y
               + __expf(20.f*f1.x)*u0.z + __expf(20.f*f1.y)*u0.w
               + __expf(20.f*f2.x)*u1.x + __expf(20.f*f2.y)*u1.y
               + __expf(20.f*f3.x)*u1.z + __expf(20.f*f3.y)*u1.w;
        }
        #pragma unroll
        for (int o=16;o;o>>=1) s += __shfl_xor_sync(0xFFFFFFFFu, s, o);
        if (lane == 0) s_v[wid*8+r] = 1.f / (16384.f * s);
    }
    __syncthreads();
    float t8[8] = {0.f,0.f,0.f,0.f,0.f,0.f,0.f,0.f};
    const uint4* base = reinterpret_cast<const uint4*>(L) + tid;
    for (int r=0; r<64; r++){
        float vv = s_v[r];
        uint4 x = base[(size_t)(b0+r)*256];
        float2 f0 = b2f(x.x), f1 = b2f(x.y), f2 = b2f(x.z), f3 = b2f(x.w);
        t8[0] += __expf(20.f*f0.x)*vv; t8[1] += __expf(20.f*f0.y)*vv;
        t8[2] += __expf(20.f*f1.x)*vv; t8[3] += __expf(20.f*f1.y)*vv;
        t8[4] += __expf(20.f*f2.x)*vv; t8[5] += __expf(20.f*f2.y)*vv;
        t8[6] += __expf(20.f*f3.x)*vv; t8[7] += __expf(20.f*f3.y)*vv;
    }
    #pragma unroll
    for (int j=0;j<8;j++) atomicAdd(&g_t[view][iter][tid*8+j], t8[j]);
}

// ===== fused final: v + lse/argmax (inline) + CE/avg_probs/acc/hist =====
__global__ void k_final(){
    __shared__ float s_avgp[2048];
    __shared__ float s_us1[2048], s_us2[2048];
    __shared__ float s_v1[16], s_v2[16];
    __shared__ double smd[256];
    __shared__ float wmx1[8], wmx2[8], wse1[8], wse2[8];
    __shared__ int wix1[8], wix2[8];
    __shared__ float wtm1[8], wtm2[8];      // tgt argmax warp results
    __shared__ int wti1[8], wti2[8];
    __shared__ float b_ls1, b_ls2;
    int tid = threadIdx.x, lane = tid & 31, wid = tid >> 5;
    int kbase = tid*8;
    float U1[8],U2[8],LU1[8],LU2[8];
    #pragma unroll
    for (int j=0;j<8;j++){
        float t1 = g_t[0][2][kbase+j];
        float t2 = g_t[1][2][kbase+j];
        float u1 = 1.f / (2048.f * t1);
        float u2 = 1.f / (2048.f * t2);
        U1[j]=u1; U2[j]=u2;
        LU1[j]=logf(u1); LU2[j]=logf(u2);
        s_avgp[kbase+j]=0.f;
        s_us1[kbase+j]=u1; s_us2[kbase+j]=u2;
    }
    __syncthreads();
    int b0 = blockIdx.x*16;
    #pragma unroll
    for (int rr=0; rr<2; rr++){
        int r = wid*2 + rr;
        int b = b0 + r;
        const uint4* L1r = reinterpret_cast<const uint4*>(g_Lb1 + (size_t)b*2048);
        const uint4* L2r = reinterpret_cast<const uint4*>(g_Lb2 + (size_t)b*2048);
        float s1 = 0.f, s2 = 0.f;
        #pragma unroll
        for (int j=0; j<8; j++){
            int c8 = j*32 + lane;
            uint4 x = L1r[c8];
            const float4* up = reinterpret_cast<const float4*>(&s_us1[c8*8]);
            float4 u0 = up[0], u1 = up[1];
            float2 f0 = b2f(x.x), f1 = b2f(x.y), f2 = b2f(x.z), f3 = b2f(x.w);
            s1 += __expf(20.f*f0.x)*u0.x + __expf(20.f*f0.y)*u0.y
                + __expf(20.f*f1.x)*u0.z + __expf(20.f*f1.y)*u0.w
                + __expf(20.f*f2.x)*u1.x + __expf(20.f*f2.y)*u1.y
                + __expf(20.f*f3.x)*u1.z + __expf(20.f*f3.y)*u1.w;
            uint4 y = L2r[c8];
            const float4* vp = reinterpret_cast<const float4*>(&s_us2[c8*8]);
            float4 v0 = vp[0], v1 = vp[1];
            float2 g0 = b2f(y.x), g1 = b2f(y.y), g2 = b2f(y.z), g3 = b2f(y.w);
            s2 += __expf(20.f*g0.x)*v0.x + __expf(20.f*g0.y)*v0.y
                + __expf(20.f*g1.x)*v0.z + __expf(20.f*g1.y)*v0.w
                + __expf(20.f*g2.x)*v1.x + __expf(20.f*g2.y)*v1.y
                + __expf(20.f*g3.x)*v1.z + __expf(20.f*g3.y)*v1.w;
        }
        #pragma unroll
        for (int o=16;o;o>>=1){
            s1 += __shfl_xor_sync(0xFFFFFFFFu, s1, o);
            s2 += __shfl_xor_sync(0xFFFFFFFFu, s2, o);
        }
        if (lane == 0){ s_v1[r] = s1; s_v2[r] = s2; }
    }
    __syncthreads();
    double tce1=0.0, tce2=0.0;
    int tacc1=0, tacc2=0;
    for (int r=0;r<16;r++){
        int b = b0 + r;
        const float4* L1r = reinterpret_cast<const float4*>(g_L1 + (size_t)b*2048);
        const float4* L2r = reinterpret_cast<const float4*>(g_L2 + (size_t)b*2048);
        float4 a0=L1r[tid*2], a1=L1r[tid*2+1];
        float4 c0=L2r[tid*2], c1=L2r[tid*2+1];
        float A[8]={a0.x,a0.y,a0.z,a0.w,a1.x,a1.y,a1.z,a1.w};
        float C[8]={c0.x,c0.y,c0.z,c0.w,c1.x,c1.y,c1.z,c1.w};
        float mA=-1e30f, seA=0.f; int iA=kbase;
        float mC=-1e30f, seC=0.f; int iC=kbase;
        float e10A[8], e10C[8];
        #pragma unroll
        for (int j=0;j<8;j++){
            float eA = __expf(10.f*A[j]); e10A[j]=eA; seA += eA;
            float eC = __expf(10.f*C[j]); e10C[j]=eC; seC += eC;
            if (A[j] > mA){ mA = A[j]; iA = kbase+j; }
            if (C[j] > mC){ mC = C[j]; iC = kbase+j; }
        }
        #pragma unroll
        for (int o=16;o;o>>=1){
            float moA = __shfl_xor_sync(0xFFFFFFFFu, mA, o);
            int   ioA = __shfl_xor_sync(0xFFFFFFFFu, iA, o);
            float moC = __shfl_xor_sync(0xFFFFFFFFu, mC, o);
            int   ioC = __shfl_xor_sync(0xFFFFFFFFu, iC, o);
            seA += __shfl_xor_sync(0xFFFFFFFFu, seA, o);
            seC += __shfl_xor_sync(0xFFFFFFFFu, seC, o);
            if (moA > mA || (moA == mA && ioA < iA)){ mA = moA; iA = ioA; }
            if (moC > mC || (moC == mC && ioC < iC)){ mC = moC; iC = ioC; }
        }
        if (lane == 0){ wmx1[wid]=mA; wix1[wid]=iA; wse1[wid]=seA;
                        wmx2[wid]=mC; wix2[wid]=iC; wse2[wid]=seC; }
        __syncthreads();
        // every thread computes the block lse/argmax from the 8 warp slots (no tid-0 serialization)
        float M1=wmx1[0], M2=wmx2[0]; int I1=wix1[0], I2=wix2[0];
        float S1=wse1[0], S2=wse2[0];
        #pragma unroll
        for (int w=1;w<8;w++){
            S1 += wse1[w]; S2 += wse2[w];
            if (wmx1[w]>M1 || (wmx1[w]==M1 && wix1[w]<I1)){ M1=wmx1[w]; I1=wix1[w]; }
            if (wmx2[w]>M2 || (wmx2[w]==M2 && wix2[w]<I2)){ M2=wmx2[w]; I2=wix2[w]; }
        }
        float ls1 = logf(S1), ls2 = logf(S2);
        int am1 = I1, am2 = I2;
        if (tid == 0){
            atomicAdd(&g_hist[I1], 1);
            atomicAdd(&g_hist[I2], 1);
        }
        float cv1 = 1.f / s_v1[r], cv2 = 1.f / s_v2[r];
        float irs1 = __expf(-ls1), irs2 = __expf(-ls2);
        float sc1=0.f, sc2=0.f;
        float m1=-1e30f, m2=-1e30f; int i1=0, i2=0;
        #pragma unroll
        for (int j=0;j<8;j++){
            float a=A[j], c=C[j];
            float lp1 = 10.f*a - ls1;
            float lp2 = 10.f*c - ls2;
            float t1 = cv1*U1[j]*e10A[j]*e10A[j];
            float t2 = cv2*U2[j]*e10C[j]*e10C[j];
            sc1 += t1*lp2;
            sc2 += t2*lp1;
            s_avgp[kbase+j] += e10A[j]*irs1 + e10C[j]*irs2;
            float g1 = 20.f*a + LU1[j];
            if (g1>m1){ m1=g1; i1=kbase+j; }
            float g2 = 20.f*c + LU2[j];
            if (g2>m2){ m2=g2; i2=kbase+j; }
        }
        tce1 += (double)sc1; tce2 += (double)sc2;
        // combined warp-shuffle argmax for both tgt distributions
        #pragma unroll
        for (int o=16;o;o>>=1){
            float mo1 = __shfl_xor_sync(0xFFFFFFFFu, m1, o);
            int   io1 = __shfl_xor_sync(0xFFFFFFFFu, i1, o);
            float mo2 = __shfl_xor_sync(0xFFFFFFFFu, m2, o);
            int   io2 = __shfl_xor_sync(0xFFFFFFFFu, i2, o);
            if (mo1 > m1 || (mo1 == m1 && io1 < i1)){ m1 = mo1; i1 = io1; }
            if (mo2 > m2 || (mo2 == m2 && io2 < i2)){ m2 = mo2; i2 = io2; }
        }
        if (lane == 0){ wtm1[wid]=m1; wti1[wid]=i1; wtm2[wid]=m2; wti2[wid]=i2; }
        __syncthreads();
        if (tid == 0){
            float N1=wtm1[0], N2=wtm2[0]; int J1=wti1[0], J2=wti2[0];
            #pragma unroll
            for (int w=1;w<8;w++){
                if (wtm1[w]>N1 || (wtm1[w]==N1 && wti1[w]<J1)){ N1=wtm1[w]; J1=wti1[w]; }
                if (wtm2[w]>N2 || (wtm2[w]==N2 && wti2[w]<J2)){ N2=wtm2[w]; J2=wti2[w]; }
            }
            if (J2 == am1) tacc1++;
            if (J1 == am2) tacc2++;
        }
        __syncthreads();
    }
    smd[tid]=tce1; __syncthreads();
    for (int o=128;o;o>>=1){ if (tid<o) smd[tid]+=smd[tid+o]; __syncthreads(); }
    if (tid==0) atomicAdd(&g_ce[0], smd[0]);
    __syncthreads();
    smd[tid]=tce2; __syncthreads();
    for (int o=128;o;o>>=1){ if (tid<o) smd[tid]+=smd[tid+o]; __syncthreads(); }
    if (tid==0) atomicAdd(&g_ce[1], smd[0]);
    __syncthreads();
    #pragma unroll
    for (int j=0;j<8;j++) atomicAdd(&g_avgp[kbase+j], s_avgp[kbase+j]);
    if (tid==0){ atomicAdd(&g_accc[0], tacc1); atomicAdd(&g_accc[1], tacc2); }
}

__global__ void k_finalize(float* __restrict__ out){
    __shared__ double smd[256];
    int tid = threadIdx.x;
    double sh=0.0, sp=0.0;
    for (int j=0;j<8;j++){
        int k = tid*8 + j;
        double hp = (double)g_hist[k] / 32768.0;
        sh += hp * log(hp + 1e-7);
        double pp = (double)g_avgp[k] / 32768.0;
        sp += pp * log(pp + 1e-7);
    }
    smd[tid]=sh; __syncthreads();
    for (int o=128;o;o>>=1){ if (tid<o) smd[tid]+=smd[tid+o]; __syncthreads(); }
    double H = smd[0]; __syncthreads();
    smd[tid]=sp; __syncthreads();
    for (int o=128;o;o>>=1){ if (tid<o) smd[tid]+=smd[tid+o]; __syncthreads(); }
    double P = smd[0];
    if (tid==0){
        double ce = -0.5 * (g_ce[0]/16384.0 + g_ce[1]/16384.0);
        float lvar = g_misc[0] + g_misc[2];
        float lcov = g_misc[1] + g_misc[3];
        double loss = 15.0*ce + (double)lvar + (double)lcov;
        out[0] = (float)loss;
        out[1] = (float)ce;
        out[2] = lvar;
        out[3] = lcov;
        out[4] = (float)exp(-H);
        out[5] = (float)exp(-P);
        out[6] = 0.5f * ((float)g_accc[0] + (float)g_accc[1]) / 16384.f;
    }
}

// ======================= launch =======================
extern "C" void kernel_launch(void* const* d_in, const int* in_sizes, int n_in,
                              void* d_out, int out_size){
    const float* z1 = (const float*)d_in[0];
    const float* z2 = (const float*)d_in[1];
    const float* W  = (const float*)d_in[2];
    float* out = (float*)d_out;

    cudaFuncSetAttribute(k_mma_all, cudaFuncAttributeMaxDynamicSharedMemorySize, G_SMEM);

    k_wsplit<<<2048,512>>>(W);                      // 0
    k_zero_main<<<1024,256>>>();                    // 1
    k_rownorm<<<Bn,128>>>(z1, 0);                   // 2
    k_rownorm<<<Bn,128>>>(z2, 1);                   // 3
    k_ztrans<<<dim3(16,512),dim3(32,8)>>>(z1, 0);   // 4
    k_ztrans<<<dim3(16,512),dim3(32,8)>>>(z2, 1);   // 5
    k_mma_all<<<5760,256,G_SMEM>>>();               // 6  all 6 GEMMs (BK=64)
    k_covfin<<<dim3(512,2),512>>>();                // 7
    k_colpass0<<<dim3(8,128,2),256>>>();            // 8
    k_rowcol<<<dim3(256,2),256>>>(1);               // 9
    k_rowcol<<<dim3(256,2),256>>>(2);               // 10
    k_final<<<1024,256>>>();                        // 11
    k_finalize<<<1,256>>>(out);                     // 12
}